// round 10
// baseline (speedup 1.0000x reference)
#include <cuda_runtime.h>
#include <cuda_bf16.h>
#include <math.h>
#include <cstdint>

#define BB 512
#define CC 12
#define WW 4
#define FF 512
#define NN 2048      // B*W
#define G3 1536      // 3*F
#define MROWS 24576  // C*N rows

// ---------------- scratch (device globals; no allocation allowed) ----------
__device__ float g_xW [MROWS * G3];    // [C][N][3F] input gate preacts
__device__ float g_hs [CC * NN * FF];  // [C][N][F]  h after each step
__device__ float g_y1 [BB * CC * FF];
__device__ float g_y2 [BB * CC];
__device__ float g_am [CC * CC];
__device__ float g_cheb[4 * CC * CC];
__device__ float g_h1 [MROWS * FF];    // [C][N][F]
__device__ float g_h2 [MROWS * FF];
__device__ float g_supp[MROWS * FF];
__device__ float g_pool[BB * CC * FF]; // [B, C*F]
__device__ float g_fcpart[8 * 512 * 512];
__device__ float g_z1 [BB * 512];
__device__ float g_z2 [BB * 512];
// bf16 hi/lo planes for tensor-core GEMMs
__device__ __nv_bfloat16 g_axh [MROWS * FF], g_axl [MROWS * FF];   // gathered x
__device__ __nv_bfloat16 g_hbh [CC * NN * FF], g_hbl [CC * NN * FF]; // GRU h
__device__ __nv_bfloat16 g_h1bh[MROWS * FF], g_h1bl[MROWS * FF];   // GCN h1
__device__ __nv_bfloat16 g_wihh[G3 * FF], g_wihl[G3 * FF];
__device__ __nv_bfloat16 g_whhh[G3 * FF], g_whhl[G3 * FF];
__device__ __nv_bfloat16 g_g0h [FF * FF], g_g0l [FF * FF];         // gcnw0^T [N,K]
__device__ __nv_bfloat16 g_g1h [FF * FF], g_g1l [FF * FF];         // gcnw1^T [N,K]

#define BKP 40                      // padded k-stride (80B rows: 16B-aligned, conflict-free)

__device__ __forceinline__ void mma16816(float* d, const uint32_t* a, const uint32_t* b) {
    asm volatile(
        "mma.sync.aligned.m16n8k16.row.col.f32.bf16.bf16.f32 "
        "{%0,%1,%2,%3}, {%4,%5,%6,%7}, {%8,%9}, {%0,%1,%2,%3};\n"
        : "+f"(d[0]), "+f"(d[1]), "+f"(d[2]), "+f"(d[3])
        : "r"(a[0]), "r"(a[1]), "r"(a[2]), "r"(a[3]), "r"(b[0]), "r"(b[1]));
}
__device__ __forceinline__ void ldm_x4(uint32_t* r, uint32_t addr) {
    asm volatile("ldmatrix.sync.aligned.m8n8.x4.shared.b16 {%0,%1,%2,%3}, [%4];"
        : "=r"(r[0]), "=r"(r[1]), "=r"(r[2]), "=r"(r[3]) : "r"(addr));
}
__device__ __forceinline__ void split_bf(float v, __nv_bfloat16& h, __nv_bfloat16& l) {
    h = __float2bfloat16(v);
    l = __float2bfloat16(v - __bfloat162float(h));
}

// ================= HMMA bf16 hi/lo split GEMM (fused 3-combo) ===============
#define MATE (128 * BKP)            // 5120 elems per matrix tile
#define STAGE4 (4 * MATE)           // Ah|Al|Bh|Bl
#define GEMM_SMEM (2 * STAGE4 * 2)  // 81920 bytes (2 stages)

__global__ void __launch_bounds__(256, 2)
gemmMMA(const __nv_bfloat16* __restrict__ Ah, const __nv_bfloat16* __restrict__ Al,
        const __nv_bfloat16* __restrict__ Bh, const __nv_bfloat16* __restrict__ Bl,
        const float* __restrict__ bias, float* __restrict__ C, int M, int N, int K)
{
    extern __shared__ __align__(16) __nv_bfloat16 dyn[];
    const uint32_t Su32 = (uint32_t)__cvta_generic_to_shared(dyn);

    const int tid = threadIdx.x, wid = tid >> 5, lane = tid & 31;
    const int wm = wid & 3, wn = wid >> 2;
    const int bm = blockIdx.y * 128, bn = blockIdx.x * 128;
    const int r = lane >> 2, cq = lane & 3;

    const __nv_bfloat16* mat[4] = {
        Ah + (size_t)bm * K, Al + (size_t)bm * K,
        Bh + (size_t)bn * K, Bl + (size_t)bn * K };
    const int KCH = K >> 5;

    float acc[2][8][4];
    #pragma unroll
    for (int mi = 0; mi < 2; mi++)
        #pragma unroll
        for (int ni = 0; ni < 8; ni++)
            #pragma unroll
            for (int q = 0; q < 4; q++) acc[mi][ni][q] = 0.f;

    const int prow = tid >> 2, pc4 = (tid & 3) * 8;
    auto prefetch = [&](int c) {
        const int k0 = c << 5, st = c & 1;
        #pragma unroll
        for (int m = 0; m < 4; m++) {
            #pragma unroll
            for (int i = 0; i < 2; i++) {
                const int row = prow + i * 64;
                const uint32_t soff = (uint32_t)(st * STAGE4 + m * MATE + row * BKP + pc4) * 2;
                const __nv_bfloat16* src = mat[m] + (size_t)row * K + k0 + pc4;
                asm volatile("cp.async.ca.shared.global [%0], [%1], 16;"
                             :: "r"(Su32 + soff), "l"(src) : "memory");
            }
        }
        asm volatile("cp.async.commit_group;" ::: "memory");
    };

    prefetch(0);
    prefetch(1);
    for (int c = 0; c < KCH; c++) {
        if (c + 1 < KCH) asm volatile("cp.async.wait_group 1;" ::: "memory");
        else             asm volatile("cp.async.wait_group 0;" ::: "memory");
        __syncthreads();

        const uint32_t S = Su32 + (uint32_t)((c & 1) * STAGE4) * 2;
        const uint32_t SAh = S, SAl = S + MATE * 2, SBh = S + 2 * MATE * 2, SBl = S + 3 * MATE * 2;
        #pragma unroll
        for (int ks = 0; ks < 2; ks++) {
            const int k0 = ks * 16;
            const uint32_t aoff = (uint32_t)((wm * 32 + (lane & 15)) * BKP +
                                             k0 + ((lane >> 4) << 3)) * 2;
            const uint32_t boffbase = (uint32_t)((wn * 64 + ((lane >> 4) << 3) + (lane & 7)) * BKP +
                                                 k0 + (((lane >> 3) & 1) << 3)) * 2;
            uint32_t ah[2][4], al[2][4], bf[8][2];
            #pragma unroll
            for (int mi = 0; mi < 2; mi++) ldm_x4(ah[mi], SAh + aoff + mi * 16 * BKP * 2);
            #pragma unroll
            for (int nj = 0; nj < 4; nj++) {
                uint32_t q[4];
                ldm_x4(q, SBh + boffbase + nj * 16 * BKP * 2);
                bf[2 * nj][0] = q[0]; bf[2 * nj][1] = q[1];
                bf[2 * nj + 1][0] = q[2]; bf[2 * nj + 1][1] = q[3];
            }
            #pragma unroll
            for (int mi = 0; mi < 2; mi++)
                #pragma unroll
                for (int ni = 0; ni < 8; ni++)
                    mma16816(acc[mi][ni], ah[mi], bf[ni]);
            #pragma unroll
            for (int mi = 0; mi < 2; mi++) ldm_x4(al[mi], SAl + aoff + mi * 16 * BKP * 2);
            #pragma unroll
            for (int mi = 0; mi < 2; mi++)
                #pragma unroll
                for (int ni = 0; ni < 8; ni++)
                    mma16816(acc[mi][ni], al[mi], bf[ni]);
            #pragma unroll
            for (int nj = 0; nj < 4; nj++) {
                uint32_t q[4];
                ldm_x4(q, SBl + boffbase + nj * 16 * BKP * 2);
                bf[2 * nj][0] = q[0]; bf[2 * nj][1] = q[1];
                bf[2 * nj + 1][0] = q[2]; bf[2 * nj + 1][1] = q[3];
            }
            #pragma unroll
            for (int mi = 0; mi < 2; mi++)
                #pragma unroll
                for (int ni = 0; ni < 8; ni++)
                    mma16816(acc[mi][ni], ah[mi], bf[ni]);
        }
        __syncthreads();
        if (c + 2 < KCH) prefetch(c + 2);
    }

    #pragma unroll
    for (int mi = 0; mi < 2; mi++) {
        const int row0 = bm + wm * 32 + mi * 16 + r;
        #pragma unroll
        for (int ni = 0; ni < 8; ni++) {
            const int col = bn + wn * 64 + ni * 8 + cq * 2;
            float b0 = 0.f, b1 = 0.f;
            if (bias) { b0 = bias[col]; b1 = bias[col + 1]; }
            float2 v0 = make_float2(acc[mi][ni][0] + b0, acc[mi][ni][1] + b1);
            float2 v1 = make_float2(acc[mi][ni][2] + b0, acc[mi][ni][3] + b1);
            *(float2*)&C[(size_t)row0 * N + col] = v0;
            *(float2*)&C[(size_t)(row0 + 8) * N + col] = v1;
        }
    }
}

// ============ fused GRU step: h_prev x whh^T (all 3 gates) + gate math ======
// grid (4, 32): bx = f-chunk (128 f), by = row-chunk (64 rows). 256 thr.
// Block N = 384 (three gate groups of 128). Warp tile 32x96.
#define GRU_AROWS 64
#define GRU_BROWS 384
#define GRU_STAGE ((2 * GRU_AROWS + 2 * GRU_BROWS) * BKP)   // 35840 elems
#define GRU_SMEM (2 * GRU_STAGE * 2)                        // 143360 bytes
#define EPI_LD 388

__global__ void __launch_bounds__(256, 1)
gruStep(int t, const float* __restrict__ bhh)
{
    extern __shared__ __align__(16) __nv_bfloat16 dyn[];
    const uint32_t Su32 = (uint32_t)__cvta_generic_to_shared(dyn);

    const int tid = threadIdx.x, wid = tid >> 5, lane = tid & 31;
    const int wrow = wid & 1, wcol = wid >> 1;       // warp tile: rows wrow*32, cols wcol*96
    const int fx = blockIdx.x;                        // f-chunk
    const int m0 = blockIdx.y * GRU_AROWS;            // row base
    const int K = FF, KCH = FF >> 5;

    const __nv_bfloat16* Aph = g_hbh + (size_t)(t - 1) * NN * FF + (size_t)m0 * K;
    const __nv_bfloat16* Apl = g_hbl + (size_t)(t - 1) * NN * FF + (size_t)m0 * K;

    float acc[2][12][4];
    #pragma unroll
    for (int mi = 0; mi < 2; mi++)
        #pragma unroll
        for (int ni = 0; ni < 12; ni++)
            #pragma unroll
            for (int q = 0; q < 4; q++) acc[mi][ni][q] = 0.f;

    const uint32_t offAh = 0, offAl = GRU_AROWS * BKP;
    const uint32_t offBh = 2 * GRU_AROWS * BKP, offBl = offBh + GRU_BROWS * BKP;

    auto prefetch = [&](int c) {
        const int k0 = c << 5;
        const uint32_t st = (uint32_t)((c & 1) * GRU_STAGE);
        // A: 2 planes x 64 rows x 4 vec16 = 512 jobs
        #pragma unroll
        for (int j = tid; j < 512; j += 256) {
            const int p = j >> 8, rr = (j >> 2) & 63, c4 = j & 3;
            const __nv_bfloat16* src = (p ? Apl : Aph) + (size_t)rr * K + k0 + c4 * 8;
            const uint32_t dst = Su32 + (st + (p ? offAl : offAh) + rr * BKP + c4 * 8) * 2;
            asm volatile("cp.async.ca.shared.global [%0], [%1], 16;"
                         :: "r"(dst), "l"(src) : "memory");
        }
        // B: 2 planes x 384 rows x 4 vec16 = 3072 jobs
        #pragma unroll
        for (int j = tid; j < 3072; j += 256) {
            const int p = j / 1536, rem = j - p * 1536;
            const int rr = rem >> 2, c4 = rem & 3;
            const int brow = (rr >> 7) * 512 + fx * 128 + (rr & 127);
            const __nv_bfloat16* src = (p ? g_whhl : g_whhh) + (size_t)brow * K + k0 + c4 * 8;
            const uint32_t dst = Su32 + (st + (p ? offBl : offBh) + rr * BKP + c4 * 8) * 2;
            asm volatile("cp.async.ca.shared.global [%0], [%1], 16;"
                         :: "r"(dst), "l"(src) : "memory");
        }
        asm volatile("cp.async.commit_group;" ::: "memory");
    };

    prefetch(0);
    prefetch(1);
    for (int c = 0; c < KCH; c++) {
        if (c + 1 < KCH) asm volatile("cp.async.wait_group 1;" ::: "memory");
        else             asm volatile("cp.async.wait_group 0;" ::: "memory");
        __syncthreads();

        const uint32_t S = Su32 + (uint32_t)((c & 1) * GRU_STAGE) * 2;
        #pragma unroll
        for (int ks = 0; ks < 2; ks++) {
            const int k0 = ks * 16;
            const uint32_t aoff = (uint32_t)((wrow * 32 + (lane & 15)) * BKP +
                                             k0 + ((lane >> 4) << 3)) * 2;
            const uint32_t boffbase = (uint32_t)((wcol * 96 + ((lane >> 4) << 3) + (lane & 7)) * BKP +
                                                 k0 + (((lane >> 3) & 1) << 3)) * 2;
            uint32_t ah[2][4], al[2][4], bf[12][2];
            #pragma unroll
            for (int mi = 0; mi < 2; mi++)
                ldm_x4(ah[mi], S + offAh * 2 + aoff + mi * 16 * BKP * 2);
            #pragma unroll
            for (int nj = 0; nj < 6; nj++) {
                uint32_t q[4];
                ldm_x4(q, S + offBh * 2 + boffbase + nj * 16 * BKP * 2);
                bf[2 * nj][0] = q[0]; bf[2 * nj][1] = q[1];
                bf[2 * nj + 1][0] = q[2]; bf[2 * nj + 1][1] = q[3];
            }
            #pragma unroll
            for (int mi = 0; mi < 2; mi++)
                #pragma unroll
                for (int ni = 0; ni < 12; ni++)
                    mma16816(acc[mi][ni], ah[mi], bf[ni]);
            #pragma unroll
            for (int mi = 0; mi < 2; mi++)
                ldm_x4(al[mi], S + offAl * 2 + aoff + mi * 16 * BKP * 2);
            #pragma unroll
            for (int mi = 0; mi < 2; mi++)
                #pragma unroll
                for (int ni = 0; ni < 12; ni++)
                    mma16816(acc[mi][ni], al[mi], bf[ni]);
            #pragma unroll
            for (int nj = 0; nj < 6; nj++) {
                uint32_t q[4];
                ldm_x4(q, S + offBl * 2 + boffbase + nj * 16 * BKP * 2);
                bf[2 * nj][0] = q[0]; bf[2 * nj][1] = q[1];
                bf[2 * nj + 1][0] = q[2]; bf[2 * nj + 1][1] = q[3];
            }
            #pragma unroll
            for (int mi = 0; mi < 2; mi++)
                #pragma unroll
                for (int ni = 0; ni < 12; ni++)
                    mma16816(acc[mi][ni], ah[mi], bf[ni]);
        }
        __syncthreads();
        if (c + 2 < KCH) prefetch(c + 2);
    }

    // ---- epilogue: stage acc -> smem fp32, then gate math ----
    __syncthreads();
    float* sacc = (float*)dyn;
    const int ep_r = lane >> 2, ep_c2 = (lane & 3) * 2;
    #pragma unroll
    for (int mi = 0; mi < 2; mi++) {
        const int row = wrow * 32 + mi * 16 + ep_r;
        #pragma unroll
        for (int ni = 0; ni < 12; ni++) {
            const int col = wcol * 96 + ni * 8 + ep_c2;
            *(float2*)&sacc[row * EPI_LD + col] =
                make_float2(acc[mi][ni][0], acc[mi][ni][1]);
            *(float2*)&sacc[(row + 8) * EPI_LD + col] =
                make_float2(acc[mi][ni][2], acc[mi][ni][3]);
        }
    }
    __syncthreads();
    #pragma unroll
    for (int j = tid; j < GRU_AROWS * 128; j += 256) {
        const int row = j >> 7, fl = j & 127;
        const int nrow = m0 + row, fg = fx * 128 + fl;
        const float hr = sacc[row * EPI_LD + fl]       + bhh[fg];
        const float hz = sacc[row * EPI_LD + 128 + fl] + bhh[512 + fg];
        const float hn = sacc[row * EPI_LD + 256 + fl] + bhh[1024 + fg];
        const float* xw = g_xW + ((size_t)t * NN + nrow) * G3;
        const float xr = xw[fg], xz = xw[512 + fg], xn = xw[1024 + fg];
        const float hp = g_hs[((size_t)(t - 1) * NN + nrow) * FF + fg];
        const float r = 1.f / (1.f + expf(-(xr + hr)));
        const float z = 1.f / (1.f + expf(-(xz + hz)));
        const float nv = tanhf(xn + r * hn);
        const float h = (1.f - z) * nv + z * hp;
        const size_t o = ((size_t)t * NN + nrow) * FF + fg;
        g_hs[o] = h;
        split_bf(h, g_hbh[(size_t)t * NN * FF + (size_t)nrow * FF + fg],
                    g_hbl[(size_t)t * NN * FF + (size_t)nrow * FF + fg]);
    }
}

// ================= fp32 128x128 GEMM (head only) ============================
template<bool TRANSB, int AMAP, int EPI>
__global__ void __launch_bounds__(256, 2)
gemm128(const float* __restrict__ A, const float* __restrict__ B,
        const float* __restrict__ bias, float* __restrict__ C,
        int M, int N, int K, int kChunk)
{
    __shared__ float As[16][132];
    __shared__ float Bs[16][132];
    const int tid = threadIdx.x;
    const int tx = tid & 15, ty = tid >> 4;
    const int bm = blockIdx.y * 128, bn = blockIdx.x * 128;
    int ks = 0, ke = K;
    if (kChunk > 0) {
        ks = blockIdx.z * kChunk; ke = ks + kChunk;
        C += (size_t)blockIdx.z * M * N;
    }
    const int lr = tid >> 2;
    const int lc = (tid & 3) * 4;
    const int bR = tid >> 5;
    const int bC = (tid & 31) * 4;
    size_t aRow0 = (size_t)(bm + lr), aRow1 = (size_t)(bm + lr + 64);

    float4 pa0, pa1, pb0, pb1;
    auto loadg = [&](int k0) {
        pa0 = *(const float4*)&A[aRow0 * K + k0 + lc];
        pa1 = *(const float4*)&A[aRow1 * K + k0 + lc];
        if (TRANSB) {
            pb0 = *(const float4*)&B[(size_t)(bn + lr) * K + k0 + lc];
            pb1 = *(const float4*)&B[(size_t)(bn + lr + 64) * K + k0 + lc];
        } else {
            pb0 = *(const float4*)&B[(size_t)(k0 + bR) * N + bn + bC];
            pb1 = *(const float4*)&B[(size_t)(k0 + bR + 8) * N + bn + bC];
        }
    };
    unsigned long long acc[8][4];
    #pragma unroll
    for (int i = 0; i < 8; i++)
        #pragma unroll
        for (int j = 0; j < 4; j++) acc[i][j] = 0ULL;
    loadg(ks);
    for (int k0 = ks; k0 < ke; k0 += 16) {
        As[lc + 0][lr] = pa0.x; As[lc + 1][lr] = pa0.y;
        As[lc + 2][lr] = pa0.z; As[lc + 3][lr] = pa0.w;
        As[lc + 0][lr + 64] = pa1.x; As[lc + 1][lr + 64] = pa1.y;
        As[lc + 2][lr + 64] = pa1.z; As[lc + 3][lr + 64] = pa1.w;
        if (TRANSB) {
            Bs[lc + 0][lr] = pb0.x; Bs[lc + 1][lr] = pb0.y;
            Bs[lc + 2][lr] = pb0.z; Bs[lc + 3][lr] = pb0.w;
            Bs[lc + 0][lr + 64] = pb1.x; Bs[lc + 1][lr + 64] = pb1.y;
            Bs[lc + 2][lr + 64] = pb1.z; Bs[lc + 3][lr + 64] = pb1.w;
        } else {
            *(float4*)&Bs[bR][bC]     = pb0;
            *(float4*)&Bs[bR + 8][bC] = pb1;
        }
        __syncthreads();
        if (k0 + 16 < ke) loadg(k0 + 16);
        #pragma unroll
        for (int k = 0; k < 16; k++) {
            float4 a0 = *(const float4*)&As[k][ty * 4];
            float4 a1 = *(const float4*)&As[k][64 + ty * 4];
            ulonglong2 b0 = *(const ulonglong2*)&Bs[k][tx * 4];
            ulonglong2 b1 = *(const ulonglong2*)&Bs[k][64 + tx * 4];
            float ar[8] = {a0.x, a0.y, a0.z, a0.w, a1.x, a1.y, a1.z, a1.w};
            unsigned long long bp[4] = {b0.x, b0.y, b1.x, b1.y};
            #pragma unroll
            for (int i = 0; i < 8; i++) {
                unsigned long long ad;
                asm("mov.b64 %0, {%1, %1};" : "=l"(ad) : "f"(ar[i]));
                #pragma unroll
                for (int j = 0; j < 4; j++)
                    asm("fma.rn.f32x2 %0, %1, %2, %0;"
                        : "+l"(acc[i][j]) : "l"(ad), "l"(bp[j]));
            }
        }
        __syncthreads();
    }
    #pragma unroll
    for (int i = 0; i < 8; i++) {
        int gm = bm + ((i < 4) ? (ty * 4 + i) : (60 + ty * 4 + i));
        float v[8];
        #pragma unroll
        for (int j = 0; j < 4; j++)
            asm("mov.b64 {%0, %1}, %2;"
                : "=f"(v[2 * j]), "=f"(v[2 * j + 1]) : "l"(acc[i][j]));
        #pragma unroll
        for (int h = 0; h < 2; h++) {
            int gn = bn + (h ? 64 + tx * 4 : tx * 4);
            float t0 = v[h * 4], t1 = v[h * 4 + 1], t2 = v[h * 4 + 2], t3 = v[h * 4 + 3];
            if (EPI >= 1) {
                t0 += bias[gn + 0]; t1 += bias[gn + 1];
                t2 += bias[gn + 2]; t3 += bias[gn + 3];
            }
            float4 o; o.x = t0; o.y = t1; o.z = t2; o.w = t3;
            *(float4*)&C[(size_t)gm * N + gn] = o;
        }
    }
}

// ================= conversions =============================================
__global__ void k_cvt(const float* __restrict__ src, __nv_bfloat16* __restrict__ hi,
                      __nv_bfloat16* __restrict__ lo, int n) {
    int i = blockIdx.x * blockDim.x + threadIdx.x;
    if (i >= n) return;
    split_bf(src[i], hi[i], lo[i]);
}

// gcn weight [K,N] -> planes [N,K]
__global__ void k_cvtT(const float* __restrict__ W, __nv_bfloat16* __restrict__ hi,
                       __nv_bfloat16* __restrict__ lo) {
    int i = blockIdx.x * blockDim.x + threadIdx.x;
    if (i >= FF * FF) return;
    int n = i >> 9, k = i & 511;
    split_bf(W[k * FF + n], hi[i], lo[i]);
}

// gather x -> A planes [C][N][F]
__global__ void k_cvt_x(const float* __restrict__ x) {
    int idx = blockIdx.x * blockDim.x + threadIdx.x;
    if (idx >= MROWS * FF) return;
    int f = idx & 511;
    int r = idx >> 9;
    int t = r / NN, n = r - t * NN;
    int b = n >> 2, w = n & 3;
    float v = x[(((size_t)b * CC + t) * WW + w) * FF + f];
    split_bf(v, g_axh[idx], g_axl[idx]);
}

// ================= GRU gate (t=0 only) ======================================
__global__ void k_gru_gate0(const float* __restrict__ bhh) {
    int idx = blockIdx.x * blockDim.x + threadIdx.x;
    if (idx >= NN * FF) return;
    int n = idx >> 9, f = idx & 511;
    const float* xw = g_xW + (size_t)n * G3;
    float r = 1.f / (1.f + expf(-(xw[f] + bhh[f])));
    float z = 1.f / (1.f + expf(-(xw[512 + f] + bhh[512 + f])));
    float nv = tanhf(xw[1024 + f] + r * bhh[1024 + f]);
    float h = (1.f - z) * nv;
    g_hs[idx] = h;
    split_bf(h, g_hbh[idx], g_hbl[idx]);
}

// ================= graph learning ==========================================
__global__ void k_y1(const float* __restrict__ w, const float* __restrict__ b0) {
    int idx = blockIdx.x * blockDim.x + threadIdx.x;
    if (idx >= BB * CC * FF) return;
    int f = idx & 511;
    int r = idx >> 9;
    int c = r % 12, b = r / 12;
    float s = b0[0];
    #pragma unroll
    for (int wi = 0; wi < 4; wi++)
        s += g_hs[((size_t)c * NN + (b * 4 + wi)) * FF + f] * w[wi];
    g_y1[idx] = fmaxf(s, 0.f);
}

__global__ void k_y2(const float* __restrict__ w, const float* __restrict__ b1) {
    int r = blockIdx.x;
    float s = 0.f;
    for (int f = threadIdx.x; f < 512; f += 128)
        s += g_y1[(size_t)r * 512 + f] * w[f];
    __shared__ float red[4];
    for (int o = 16; o; o >>= 1) s += __shfl_down_sync(0xffffffffu, s, o);
    if ((threadIdx.x & 31) == 0) red[threadIdx.x >> 5] = s;
    __syncthreads();
    if (threadIdx.x == 0)
        g_y2[r] = fmaxf(red[0] + red[1] + red[2] + red[3] + b1[0], 0.f);
}

__global__ void k_y3mean(const float* __restrict__ w2, const float* __restrict__ b2) {
    int k = blockIdx.x;
    float wl[12];
    #pragma unroll
    for (int c = 0; c < 12; c++) wl[c] = w2[k * 12 + c];
    float bk = b2[k];
    float s = 0.f;
    for (int b = threadIdx.x; b < 512; b += 256) {
        float v = bk;
        #pragma unroll
        for (int c = 0; c < 12; c++) v += g_y2[b * 12 + c] * wl[c];
        s += fmaxf(v, 0.f);
    }
    __shared__ float red[8];
    for (int o = 16; o; o >>= 1) s += __shfl_down_sync(0xffffffffu, s, o);
    if ((threadIdx.x & 31) == 0) red[threadIdx.x >> 5] = s;
    __syncthreads();
    if (threadIdx.x == 0) {
        float t = 0.f;
        #pragma unroll
        for (int i = 0; i < 8; i++) t += red[i];
        g_am[k] = t * (1.f / 512.f);
    }
}

__global__ void k_cheb() {
    __shared__ float adj[144], lap[144], L2s[144], deg[12], dh[12];
    int t = threadIdx.x;
    if (t < 144) adj[t] = fmaxf(g_am[t], 0.f);
    __syncthreads();
    if (t < 12) {
        float s = 0.f;
        #pragma unroll
        for (int j = 0; j < 12; j++) s += adj[t * 12 + j];
        deg[t] = s;
        dh[t] = 1.f / (sqrtf(s) + 1e-7f);
    }
    __syncthreads();
    if (t < 144) {
        int i = t / 12, j = t % 12;
        float as = 0.5f * (adj[i * 12 + j] + adj[j * 12 + i]);
        lap[t] = dh[i] * (((i == j) ? deg[i] : 0.f) - as) * dh[j];
    }
    __syncthreads();
    if (t < 144) {
        int i = t / 12, j = t % 12;
        float s = 0.f;
        #pragma unroll
        for (int k = 0; k < 12; k++) s += lap[i * 12 + k] * lap[k * 12 + j];
        L2s[t] = 2.f * s;
    }
    __syncthreads();
    if (t < 144) {
        int i = t / 12, j = t % 12;
        float s = 0.f;
        #pragma unroll
        for (int k = 0; k < 12; k++) s += lap[i * 12 + k] * L2s[k * 12 + j];
        g_cheb[t]       = 0.f;
        g_cheb[144 + t] = lap[t];
        g_cheb[288 + t] = L2s[t];
        g_cheb[432 + t] = 2.f * s - lap[t];
    }
}

// ============ GCN: cheb mix + bias + relu + residual ([C][N][F]) ============
__global__ void k_gcnpost(const float* __restrict__ Hres, const float* __restrict__ gcnb,
                          float* __restrict__ Hout,
                          __nv_bfloat16* __restrict__ Ohi, __nv_bfloat16* __restrict__ Olo) {
    int blk = blockIdx.x;
    int n = blk >> 2;
    int chunk = blk & 3;
    int w = n & 3;
    int f = chunk * 128 + threadIdx.x;
    __shared__ float s[12][129];
    __shared__ float ch[144];
    for (int i = threadIdx.x; i < 144; i += 128) ch[i] = g_cheb[w * 144 + i];
    #pragma unroll
    for (int j = 0; j < 12; j++)
        s[j][threadIdx.x] = g_supp[((size_t)j * NN + n) * 512 + f];
    __syncthreads();
    float bias = gcnb[f];
    #pragma unroll
    for (int i = 0; i < 12; i++) {
        float acc = bias;
        #pragma unroll
        for (int j = 0; j < 12; j++)
            acc = fmaf(ch[i * 12 + j], s[j][threadIdx.x], acc);
        size_t o = ((size_t)i * NN + n) * 512 + f;
        float hv = fmaxf(acc, 0.f) + Hres[o];
        Hout[o] = hv;
        if (Ohi) split_bf(hv, Ohi[o], Olo[o]);
    }
}

// ================= pool over W + flatten ====================================
__global__ void k_pool() {
    int idx = blockIdx.x * blockDim.x + threadIdx.x;
    if (idx >= BB * CC * FF) return;
    int f = idx & 511;
    int r = idx >> 9;
    int c = r % 12, b = r / 12;
    float s = 0.f;
    #pragma unroll
    for (int w = 0; w < 4; w++) {
        size_t o = ((size_t)c * NN + (b * 4 + w)) * 512 + f;
        s += g_hs[o] + g_h2[o];
    }
    g_pool[idx] = s;
}

// ================= split-K reduce + leaky + BN ==============================
__global__ void k_fcreduce(int S, const float* __restrict__ bias,
                           const float* __restrict__ bng, const float* __restrict__ bnb,
                           const float* __restrict__ bnm, const float* __restrict__ bnv,
                           float* __restrict__ out) {
    int idx = blockIdx.x * blockDim.x + threadIdx.x;
    if (idx >= 512 * 512) return;
    float s = 0.f;
    for (int p = 0; p < S; p++) s += g_fcpart[(size_t)p * 512 * 512 + idx];
    int c = idx & 511;
    s += bias[c];
    s = s > 0.f ? s : 0.01f * s;
    s = (s - bnm[c]) * rsqrtf(bnv[c] + 1e-5f) * bng[c] + bnb[c];
    out[idx] = s;
}

// ================= fc3 (N=4) ================================================
__global__ void k_fc3(const float* __restrict__ w, const float* __restrict__ b,
                      float* __restrict__ out) {
    int bb = blockIdx.x;
    float s0 = 0.f, s1 = 0.f, s2 = 0.f, s3 = 0.f;
    for (int j = threadIdx.x; j < 512; j += 128) {
        float v = g_z2[bb * 512 + j];
        const float* wr = w + j * 4;
        s0 += v * wr[0]; s1 += v * wr[1]; s2 += v * wr[2]; s3 += v * wr[3];
    }
    __shared__ float red[4][4];
    for (int o = 16; o; o >>= 1) {
        s0 += __shfl_down_sync(0xffffffffu, s0, o);
        s1 += __shfl_down_sync(0xffffffffu, s1, o);
        s2 += __shfl_down_sync(0xffffffffu, s2, o);
        s3 += __shfl_down_sync(0xffffffffu, s3, o);
    }
    int wid = threadIdx.x >> 5;
    if ((threadIdx.x & 31) == 0) {
        red[wid][0] = s0; red[wid][1] = s1; red[wid][2] = s2; red[wid][3] = s3;
    }
    __syncthreads();
    if (threadIdx.x < 4) {
        float t = red[0][threadIdx.x] + red[1][threadIdx.x] +
                  red[2][threadIdx.x] + red[3][threadIdx.x];
        out[bb * 4 + threadIdx.x] = t + b[threadIdx.x];
    }
}

// ================= launch ===================================================
extern "C" void kernel_launch(void* const* d_in, const int* in_sizes, int n_in,
                              void* d_out, int out_size) {
    const float* x    = (const float*)d_in[0];
    const float* wih  = (const float*)d_in[1];
    const float* whh  = (const float*)d_in[2];
    const float* bih  = (const float*)d_in[3];
    const float* bhh  = (const float*)d_in[4];
    const float* c0w  = (const float*)d_in[5];
    const float* c0b  = (const float*)d_in[6];
    const float* c1w  = (const float*)d_in[7];
    const float* c1b  = (const float*)d_in[8];
    const float* c2w  = (const float*)d_in[9];
    const float* c2b  = (const float*)d_in[10];
    const float* gcnw = (const float*)d_in[11];
    const float* gcnb = (const float*)d_in[12];
    const float* fc1w = (const float*)d_in[13];
    const float* fc1b = (const float*)d_in[14];
    const float* bn1g = (const float*)d_in[15];
    const float* bn1b = (const float*)d_in[16];
    const float* bn1m = (const float*)d_in[17];
    const float* bn1v = (const float*)d_in[18];
    const float* fc2w = (const float*)d_in[19];
    const float* fc2b = (const float*)d_in[20];
    const float* bn2g = (const float*)d_in[21];
    const float* bn2b = (const float*)d_in[22];
    const float* bn2m = (const float*)d_in[23];
    const float* bn2v = (const float*)d_in[24];
    const float* fc3w = (const float*)d_in[25];
    const float* fc3b = (const float*)d_in[26];
    float* out = (float*)d_out;

    cudaFuncSetAttribute(gemmMMA, cudaFuncAttributeMaxDynamicSharedMemorySize, GEMM_SMEM);
    cudaFuncSetAttribute(gruStep, cudaFuncAttributeMaxDynamicSharedMemorySize, GRU_SMEM);

    float *p_xW, *p_h1, *p_h2, *p_supp, *p_pool, *p_part, *p_z1, *p_z2, *p_hs;
    cudaGetSymbolAddress((void**)&p_xW,  g_xW);
    cudaGetSymbolAddress((void**)&p_hs,  g_hs);
    cudaGetSymbolAddress((void**)&p_h1,  g_h1);
    cudaGetSymbolAddress((void**)&p_h2,  g_h2);
    cudaGetSymbolAddress((void**)&p_supp, g_supp);
    cudaGetSymbolAddress((void**)&p_pool, g_pool);
    cudaGetSymbolAddress((void**)&p_part, g_fcpart);
    cudaGetSymbolAddress((void**)&p_z1,  g_z1);
    cudaGetSymbolAddress((void**)&p_z2,  g_z2);
    __nv_bfloat16 *p_axh, *p_axl, *p_hbh, *p_hbl, *p_h1bh, *p_h1bl;
    __nv_bfloat16 *p_wihh, *p_wihl, *p_whhh, *p_whhl, *p_g0h, *p_g0l, *p_g1h, *p_g1l;
    cudaGetSymbolAddress((void**)&p_axh,  g_axh);
    cudaGetSymbolAddress((void**)&p_axl,  g_axl);
    cudaGetSymbolAddress((void**)&p_hbh,  g_hbh);
    cudaGetSymbolAddress((void**)&p_hbl,  g_hbl);
    cudaGetSymbolAddress((void**)&p_h1bh, g_h1bh);
    cudaGetSymbolAddress((void**)&p_h1bl, g_h1bl);
    cudaGetSymbolAddress((void**)&p_wihh, g_wihh);
    cudaGetSymbolAddress((void**)&p_wihl, g_wihl);
    cudaGetSymbolAddress((void**)&p_whhh, g_whhh);
    cudaGetSymbolAddress((void**)&p_whhl, g_whhl);
    cudaGetSymbolAddress((void**)&p_g0h,  g_g0h);
    cudaGetSymbolAddress((void**)&p_g0l,  g_g0l);
    cudaGetSymbolAddress((void**)&p_g1h,  g_g1h);
    cudaGetSymbolAddress((void**)&p_g1l,  g_g1l);

    // 0) input-side conversions
    k_cvt_x<<<(MROWS * FF + 255) / 256, 256>>>(x);
    k_cvt<<<(G3 * FF + 255) / 256, 256>>>(wih, p_wihh, p_wihl, G3 * FF);
    k_cvt<<<(G3 * FF + 255) / 256, 256>>>(whh, p_whhh, p_whhl, G3 * FF);

    // 1) input-gate preacts: [24576,1536] = x * wih^T + bih  (HMMA)
    gemmMMA<<<dim3(G3 / 128, MROWS / 128), 256, GEMM_SMEM>>>(
        p_axh, p_axl, p_wihh, p_wihl, bih, p_xW, MROWS, G3, FF);

    // 2) 12 recurrent steps: t=0 gate-only, then 11 fused GEMM+gate steps
    k_gru_gate0<<<(NN * FF + 255) / 256, 256>>>(bhh);
    for (int t = 1; t < CC; t++)
        gruStep<<<dim3(4, 32), 256, GRU_SMEM>>>(t, bhh);

    // 3) graph learning -> chebyshev basis (+ GCN weight conversion)
    k_y1<<<(BB * CC * FF + 255) / 256, 256>>>(c0w, c0b);
    k_y2<<<BB * CC, 128>>>(c1w, c1b);
    k_y3mean<<<CC * CC, 256>>>(c2w, c2b);
    k_cheb<<<1, 160>>>();
    k_cvtT<<<(FF * FF + 255) / 256, 256>>>(gcnw, p_g0h, p_g0l);
    k_cvtT<<<(FF * FF + 255) / 256, 256>>>(gcnw + FF * FF, p_g1h, p_g1l);

    // 4) GCN layer 0
    gemmMMA<<<dim3(FF / 128, MROWS / 128), 256, GEMM_SMEM>>>(
        p_hbh, p_hbl, p_g0h, p_g0l, nullptr, p_supp, MROWS, FF, FF);
    k_gcnpost<<<NN * 4, 128>>>(p_hs, gcnb, p_h1, p_h1bh, p_h1bl);

    // 5) GCN layer 1
    gemmMMA<<<dim3(FF / 128, MROWS / 128), 256, GEMM_SMEM>>>(
        p_h1bh, p_h1bl, p_g1h, p_g1l, nullptr, p_supp, MROWS, FF, FF);
    k_gcnpost<<<NN * 4, 128>>>(p_h1, gcnb + FF, p_h2, nullptr, nullptr);

    // 6) pool over W -> [B, C*F]
    k_pool<<<(BB * CC * FF + 255) / 256, 256>>>();

    // 7) classifier head (fp32 split-K)
    gemm128<false, 0, 0><<<dim3(4, 4, 8), 256>>>(
        p_pool, fc1w, nullptr, p_part, BB, 512, CC * FF, 768);
    k_fcreduce<<<1024, 256>>>(8, fc1b, bn1g, bn1b, bn1m, bn1v, p_z1);
    gemm128<false, 0, 0><<<dim3(4, 4, 4), 256>>>(
        p_z1, fc2w, nullptr, p_part, BB, 512, 512, 128);
    k_fcreduce<<<1024, 256>>>(4, fc2b, bn2g, bn2b, bn2m, bn2v, p_z2);
    k_fc3<<<BB, 128>>>(fc3w, fc3b, out);
}

// round 11
// speedup vs baseline: 1.1626x; 1.1626x over previous
#include <cuda_runtime.h>
#include <cuda_bf16.h>
#include <math.h>
#include <cstdint>

#define BB 512
#define CC 12
#define WW 4
#define FF 512
#define NN 2048      // B*W
#define G3 1536      // 3*F
#define MROWS 24576  // C*N rows

// ---------------- scratch (device globals; no allocation allowed) ----------
__device__ float g_xW [MROWS * G3];    // [C][N][3F] input gate preacts
__device__ float g_hgp[2 * NN * G3];   // split-K partials for recurrent GEMM
__device__ float g_hs [CC * NN * FF];  // [C][N][F]  h after each step
__device__ float g_y1 [BB * CC * FF];
__device__ float g_y2 [BB * CC];
__device__ float g_am [CC * CC];
__device__ float g_cheb[4 * CC * CC];
__device__ float g_h1 [MROWS * FF];    // [C][N][F]
__device__ float g_h2 [MROWS * FF];
__device__ float g_supp[MROWS * FF];
__device__ float g_pool[BB * CC * FF]; // [B, C*F]
__device__ float g_fcpart[8 * 512 * 512];
__device__ float g_z1 [BB * 512];
__device__ float g_z2 [BB * 512];
// bf16 hi/lo planes for tensor-core GEMMs
__device__ __nv_bfloat16 g_axh [MROWS * FF], g_axl [MROWS * FF];   // gathered x
__device__ __nv_bfloat16 g_hbh [CC * NN * FF], g_hbl [CC * NN * FF]; // GRU h
__device__ __nv_bfloat16 g_h1bh[MROWS * FF], g_h1bl[MROWS * FF];   // GCN h1
__device__ __nv_bfloat16 g_wihh[G3 * FF], g_wihl[G3 * FF];
__device__ __nv_bfloat16 g_whhh[G3 * FF], g_whhl[G3 * FF];
__device__ __nv_bfloat16 g_g0h [FF * FF], g_g0l [FF * FF];         // gcnw0^T [N,K]
__device__ __nv_bfloat16 g_g1h [FF * FF], g_g1l [FF * FF];         // gcnw1^T [N,K]

#define BKP 40                      // padded k-stride (80B rows: 16B-aligned, conflict-free)

__device__ __forceinline__ void mma16816(float* d, const uint32_t* a, const uint32_t* b) {
    asm volatile(
        "mma.sync.aligned.m16n8k16.row.col.f32.bf16.bf16.f32 "
        "{%0,%1,%2,%3}, {%4,%5,%6,%7}, {%8,%9}, {%0,%1,%2,%3};\n"
        : "+f"(d[0]), "+f"(d[1]), "+f"(d[2]), "+f"(d[3])
        : "r"(a[0]), "r"(a[1]), "r"(a[2]), "r"(a[3]), "r"(b[0]), "r"(b[1]));
}
__device__ __forceinline__ void ldm_x4(uint32_t* r, uint32_t addr) {
    asm volatile("ldmatrix.sync.aligned.m8n8.x4.shared.b16 {%0,%1,%2,%3}, [%4];"
        : "=r"(r[0]), "=r"(r[1]), "=r"(r[2]), "=r"(r[3]) : "r"(addr));
}
__device__ __forceinline__ void split_bf(float v, __nv_bfloat16& h, __nv_bfloat16& l) {
    h = __float2bfloat16(v);
    l = __float2bfloat16(v - __bfloat162float(h));
}

// ================= HMMA bf16 hi/lo split GEMM (fused 3-combo) ===============
// D[M,N] fp32 = (Ah+Al)*(Bh+Bl)^T - Al*Bl^T  (lo*lo dropped)
// kSplit>1: grid.z splits the K range; partial z written to C + z*M*N.
#define MATE (128 * BKP)            // 5120 elems per matrix tile
#define STAGE4 (4 * MATE)           // Ah|Al|Bh|Bl
#define GEMM_SMEM (2 * STAGE4 * 2)  // 81920 bytes (2 stages)

__global__ void __launch_bounds__(256, 2)
gemmMMA(const __nv_bfloat16* __restrict__ Ah, const __nv_bfloat16* __restrict__ Al,
        const __nv_bfloat16* __restrict__ Bh, const __nv_bfloat16* __restrict__ Bl,
        const float* __restrict__ bias, float* __restrict__ C, int M, int N, int K,
        int kSplit)
{
    extern __shared__ __align__(16) __nv_bfloat16 dyn[];
    const uint32_t Su32 = (uint32_t)__cvta_generic_to_shared(dyn);

    const int tid = threadIdx.x, wid = tid >> 5, lane = tid & 31;
    const int wm = wid & 3, wn = wid >> 2;
    const int bm = blockIdx.y * 128, bn = blockIdx.x * 128;
    const int r = lane >> 2, cq = lane & 3;

    const __nv_bfloat16* mat[4] = {
        Ah + (size_t)bm * K, Al + (size_t)bm * K,
        Bh + (size_t)bn * K, Bl + (size_t)bn * K };
    const int KCH = K >> 5;
    const int cps = KCH / kSplit;                     // chunks per split
    const int c0 = blockIdx.z * cps, c1 = c0 + cps;
    C += (size_t)blockIdx.z * M * N;

    float acc[2][8][4];
    #pragma unroll
    for (int mi = 0; mi < 2; mi++)
        #pragma unroll
        for (int ni = 0; ni < 8; ni++)
            #pragma unroll
            for (int q = 0; q < 4; q++) acc[mi][ni][q] = 0.f;

    const int prow = tid >> 2, pc4 = (tid & 3) * 8;
    auto prefetch = [&](int c) {
        const int k0 = c << 5, st = c & 1;
        #pragma unroll
        for (int m = 0; m < 4; m++) {
            #pragma unroll
            for (int i = 0; i < 2; i++) {
                const int row = prow + i * 64;
                const uint32_t soff = (uint32_t)(st * STAGE4 + m * MATE + row * BKP + pc4) * 2;
                const __nv_bfloat16* src = mat[m] + (size_t)row * K + k0 + pc4;
                asm volatile("cp.async.ca.shared.global [%0], [%1], 16;"
                             :: "r"(Su32 + soff), "l"(src) : "memory");
            }
        }
        asm volatile("cp.async.commit_group;" ::: "memory");
    };

    prefetch(c0);
    if (c0 + 1 < c1) prefetch(c0 + 1);
    for (int c = c0; c < c1; c++) {
        if (c + 1 < c1) asm volatile("cp.async.wait_group 1;" ::: "memory");
        else            asm volatile("cp.async.wait_group 0;" ::: "memory");
        __syncthreads();

        const uint32_t S = Su32 + (uint32_t)((c & 1) * STAGE4) * 2;
        const uint32_t SAh = S, SAl = S + MATE * 2, SBh = S + 2 * MATE * 2, SBl = S + 3 * MATE * 2;
        #pragma unroll
        for (int ks = 0; ks < 2; ks++) {
            const int k0 = ks * 16;
            const uint32_t aoff = (uint32_t)((wm * 32 + (lane & 15)) * BKP +
                                             k0 + ((lane >> 4) << 3)) * 2;
            const uint32_t boffbase = (uint32_t)((wn * 64 + ((lane >> 4) << 3) + (lane & 7)) * BKP +
                                                 k0 + (((lane >> 3) & 1) << 3)) * 2;
            uint32_t ah[2][4], al[2][4], bf[8][2];
            #pragma unroll
            for (int mi = 0; mi < 2; mi++) ldm_x4(ah[mi], SAh + aoff + mi * 16 * BKP * 2);
            #pragma unroll
            for (int nj = 0; nj < 4; nj++) {
                uint32_t q[4];
                ldm_x4(q, SBh + boffbase + nj * 16 * BKP * 2);
                bf[2 * nj][0] = q[0]; bf[2 * nj][1] = q[1];
                bf[2 * nj + 1][0] = q[2]; bf[2 * nj + 1][1] = q[3];
            }
            #pragma unroll
            for (int mi = 0; mi < 2; mi++)
                #pragma unroll
                for (int ni = 0; ni < 8; ni++)
                    mma16816(acc[mi][ni], ah[mi], bf[ni]);
            #pragma unroll
            for (int mi = 0; mi < 2; mi++) ldm_x4(al[mi], SAl + aoff + mi * 16 * BKP * 2);
            #pragma unroll
            for (int mi = 0; mi < 2; mi++)
                #pragma unroll
                for (int ni = 0; ni < 8; ni++)
                    mma16816(acc[mi][ni], al[mi], bf[ni]);
            #pragma unroll
            for (int nj = 0; nj < 4; nj++) {
                uint32_t q[4];
                ldm_x4(q, SBl + boffbase + nj * 16 * BKP * 2);
                bf[2 * nj][0] = q[0]; bf[2 * nj][1] = q[1];
                bf[2 * nj + 1][0] = q[2]; bf[2 * nj + 1][1] = q[3];
            }
            #pragma unroll
            for (int mi = 0; mi < 2; mi++)
                #pragma unroll
                for (int ni = 0; ni < 8; ni++)
                    mma16816(acc[mi][ni], ah[mi], bf[ni]);
        }
        __syncthreads();
        if (c + 2 < c1) prefetch(c + 2);
    }

    #pragma unroll
    for (int mi = 0; mi < 2; mi++) {
        const int row0 = bm + wm * 32 + mi * 16 + r;
        #pragma unroll
        for (int ni = 0; ni < 8; ni++) {
            const int col = bn + wn * 64 + ni * 8 + cq * 2;
            float b0 = 0.f, b1 = 0.f;
            if (bias) { b0 = bias[col]; b1 = bias[col + 1]; }
            float2 v0 = make_float2(acc[mi][ni][0] + b0, acc[mi][ni][1] + b1);
            float2 v1 = make_float2(acc[mi][ni][2] + b0, acc[mi][ni][3] + b1);
            *(float2*)&C[(size_t)row0 * N + col] = v0;
            *(float2*)&C[(size_t)(row0 + 8) * N + col] = v1;
        }
    }
}

// ================= fp32 128x128 GEMM (head only) ============================
template<bool TRANSB, int AMAP, int EPI>
__global__ void __launch_bounds__(256, 2)
gemm128(const float* __restrict__ A, const float* __restrict__ B,
        const float* __restrict__ bias, float* __restrict__ C,
        int M, int N, int K, int kChunk)
{
    __shared__ float As[16][132];
    __shared__ float Bs[16][132];
    const int tid = threadIdx.x;
    const int tx = tid & 15, ty = tid >> 4;
    const int bm = blockIdx.y * 128, bn = blockIdx.x * 128;
    int ks = 0, ke = K;
    if (kChunk > 0) {
        ks = blockIdx.z * kChunk; ke = ks + kChunk;
        C += (size_t)blockIdx.z * M * N;
    }
    const int lr = tid >> 2;
    const int lc = (tid & 3) * 4;
    const int bR = tid >> 5;
    const int bC = (tid & 31) * 4;
    size_t aRow0 = (size_t)(bm + lr), aRow1 = (size_t)(bm + lr + 64);

    float4 pa0, pa1, pb0, pb1;
    auto loadg = [&](int k0) {
        pa0 = *(const float4*)&A[aRow0 * K + k0 + lc];
        pa1 = *(const float4*)&A[aRow1 * K + k0 + lc];
        if (TRANSB) {
            pb0 = *(const float4*)&B[(size_t)(bn + lr) * K + k0 + lc];
            pb1 = *(const float4*)&B[(size_t)(bn + lr + 64) * K + k0 + lc];
        } else {
            pb0 = *(const float4*)&B[(size_t)(k0 + bR) * N + bn + bC];
            pb1 = *(const float4*)&B[(size_t)(k0 + bR + 8) * N + bn + bC];
        }
    };
    unsigned long long acc[8][4];
    #pragma unroll
    for (int i = 0; i < 8; i++)
        #pragma unroll
        for (int j = 0; j < 4; j++) acc[i][j] = 0ULL;
    loadg(ks);
    for (int k0 = ks; k0 < ke; k0 += 16) {
        As[lc + 0][lr] = pa0.x; As[lc + 1][lr] = pa0.y;
        As[lc + 2][lr] = pa0.z; As[lc + 3][lr] = pa0.w;
        As[lc + 0][lr + 64] = pa1.x; As[lc + 1][lr + 64] = pa1.y;
        As[lc + 2][lr + 64] = pa1.z; As[lc + 3][lr + 64] = pa1.w;
        if (TRANSB) {
            Bs[lc + 0][lr] = pb0.x; Bs[lc + 1][lr] = pb0.y;
            Bs[lc + 2][lr] = pb0.z; Bs[lc + 3][lr] = pb0.w;
            Bs[lc + 0][lr + 64] = pb1.x; Bs[lc + 1][lr + 64] = pb1.y;
            Bs[lc + 2][lr + 64] = pb1.z; Bs[lc + 3][lr + 64] = pb1.w;
        } else {
            *(float4*)&Bs[bR][bC]     = pb0;
            *(float4*)&Bs[bR + 8][bC] = pb1;
        }
        __syncthreads();
        if (k0 + 16 < ke) loadg(k0 + 16);
        #pragma unroll
        for (int k = 0; k < 16; k++) {
            float4 a0 = *(const float4*)&As[k][ty * 4];
            float4 a1 = *(const float4*)&As[k][64 + ty * 4];
            ulonglong2 b0 = *(const ulonglong2*)&Bs[k][tx * 4];
            ulonglong2 b1 = *(const ulonglong2*)&Bs[k][64 + tx * 4];
            float ar[8] = {a0.x, a0.y, a0.z, a0.w, a1.x, a1.y, a1.z, a1.w};
            unsigned long long bp[4] = {b0.x, b0.y, b1.x, b1.y};
            #pragma unroll
            for (int i = 0; i < 8; i++) {
                unsigned long long ad;
                asm("mov.b64 %0, {%1, %1};" : "=l"(ad) : "f"(ar[i]));
                #pragma unroll
                for (int j = 0; j < 4; j++)
                    asm("fma.rn.f32x2 %0, %1, %2, %0;"
                        : "+l"(acc[i][j]) : "l"(ad), "l"(bp[j]));
            }
        }
        __syncthreads();
    }
    #pragma unroll
    for (int i = 0; i < 8; i++) {
        int gm = bm + ((i < 4) ? (ty * 4 + i) : (60 + ty * 4 + i));
        float v[8];
        #pragma unroll
        for (int j = 0; j < 4; j++)
            asm("mov.b64 {%0, %1}, %2;"
                : "=f"(v[2 * j]), "=f"(v[2 * j + 1]) : "l"(acc[i][j]));
        #pragma unroll
        for (int h = 0; h < 2; h++) {
            int gn = bn + (h ? 64 + tx * 4 : tx * 4);
            float t0 = v[h * 4], t1 = v[h * 4 + 1], t2 = v[h * 4 + 2], t3 = v[h * 4 + 3];
            if (EPI >= 1) {
                t0 += bias[gn + 0]; t1 += bias[gn + 1];
                t2 += bias[gn + 2]; t3 += bias[gn + 3];
            }
            float4 o; o.x = t0; o.y = t1; o.z = t2; o.w = t3;
            *(float4*)&C[(size_t)gm * N + gn] = o;
        }
    }
}

// ================= conversions =============================================
__global__ void k_cvt(const float* __restrict__ src, __nv_bfloat16* __restrict__ hi,
                      __nv_bfloat16* __restrict__ lo, int n) {
    int i = blockIdx.x * blockDim.x + threadIdx.x;
    if (i >= n) return;
    split_bf(src[i], hi[i], lo[i]);
}

// gcn weight [K,N] -> planes [N,K]
__global__ void k_cvtT(const float* __restrict__ W, __nv_bfloat16* __restrict__ hi,
                       __nv_bfloat16* __restrict__ lo) {
    int i = blockIdx.x * blockDim.x + threadIdx.x;
    if (i >= FF * FF) return;
    int n = i >> 9, k = i & 511;
    split_bf(W[k * FF + n], hi[i], lo[i]);
}

// gather x -> A planes [C][N][F]
__global__ void k_cvt_x(const float* __restrict__ x) {
    int idx = blockIdx.x * blockDim.x + threadIdx.x;
    if (idx >= MROWS * FF) return;
    int f = idx & 511;
    int r = idx >> 9;
    int t = r / NN, n = r - t * NN;
    int b = n >> 2, w = n & 3;
    float v = x[(((size_t)b * CC + t) * WW + w) * FF + f];
    split_bf(v, g_axh[idx], g_axl[idx]);
}

// ================= GRU gates ================================================
__global__ void k_gru_gate0(const float* __restrict__ bhh) {
    int idx = blockIdx.x * blockDim.x + threadIdx.x;
    if (idx >= NN * FF) return;
    int n = idx >> 9, f = idx & 511;
    const float* xw = g_xW + (size_t)n * G3;
    float r = 1.f / (1.f + expf(-(xw[f] + bhh[f])));
    float z = 1.f / (1.f + expf(-(xw[512 + f] + bhh[512 + f])));
    float nv = tanhf(xw[1024 + f] + r * bhh[1024 + f]);
    float h = (1.f - z) * nv;
    g_hs[idx] = h;
    split_bf(h, g_hbh[idx], g_hbl[idx]);
}

// t>0: sums the two split-K partials of h_prev @ whh^T, adds bhh, gate math.
__global__ void k_gru_gate(int t, const float* __restrict__ bhh) {
    int idx = blockIdx.x * blockDim.x + threadIdx.x;
    if (idx >= NN * FF) return;
    int n = idx >> 9, f = idx & 511;
    const size_t base = (size_t)n * G3;
    const float* p0 = g_hgp + base;
    const float* p1 = g_hgp + (size_t)NN * G3 + base;
    float hr = p0[f]        + p1[f]        + bhh[f];
    float hz = p0[512 + f]  + p1[512 + f]  + bhh[512 + f];
    float hn = p0[1024 + f] + p1[1024 + f] + bhh[1024 + f];
    const float* xw = g_xW + ((size_t)t * NN + n) * G3;
    float xr = xw[f], xz = xw[512 + f], xn = xw[1024 + f];
    float hp = g_hs[((size_t)(t - 1) * NN + n) * FF + f];
    float r = 1.f / (1.f + expf(-(xr + hr)));
    float z = 1.f / (1.f + expf(-(xz + hz)));
    float nv = tanhf(xn + r * hn);
    float h = (1.f - z) * nv + z * hp;
    size_t o = ((size_t)t * NN + n) * FF + f;
    g_hs[o] = h;
    split_bf(h, g_hbh[o], g_hbl[o]);
}

// ================= graph learning ==========================================
__global__ void k_y1(const float* __restrict__ w, const float* __restrict__ b0) {
    int idx = blockIdx.x * blockDim.x + threadIdx.x;
    if (idx >= BB * CC * FF) return;
    int f = idx & 511;
    int r = idx >> 9;
    int c = r % 12, b = r / 12;
    float s = b0[0];
    #pragma unroll
    for (int wi = 0; wi < 4; wi++)
        s += g_hs[((size_t)c * NN + (b * 4 + wi)) * FF + f] * w[wi];
    g_y1[idx] = fmaxf(s, 0.f);
}

__global__ void k_y2(const float* __restrict__ w, const float* __restrict__ b1) {
    int r = blockIdx.x;
    float s = 0.f;
    for (int f = threadIdx.x; f < 512; f += 128)
        s += g_y1[(size_t)r * 512 + f] * w[f];
    __shared__ float red[4];
    for (int o = 16; o; o >>= 1) s += __shfl_down_sync(0xffffffffu, s, o);
    if ((threadIdx.x & 31) == 0) red[threadIdx.x >> 5] = s;
    __syncthreads();
    if (threadIdx.x == 0)
        g_y2[r] = fmaxf(red[0] + red[1] + red[2] + red[3] + b1[0], 0.f);
}

__global__ void k_y3mean(const float* __restrict__ w2, const float* __restrict__ b2) {
    int k = blockIdx.x;
    float wl[12];
    #pragma unroll
    for (int c = 0; c < 12; c++) wl[c] = w2[k * 12 + c];
    float bk = b2[k];
    float s = 0.f;
    for (int b = threadIdx.x; b < 512; b += 256) {
        float v = bk;
        #pragma unroll
        for (int c = 0; c < 12; c++) v += g_y2[b * 12 + c] * wl[c];
        s += fmaxf(v, 0.f);
    }
    __shared__ float red[8];
    for (int o = 16; o; o >>= 1) s += __shfl_down_sync(0xffffffffu, s, o);
    if ((threadIdx.x & 31) == 0) red[threadIdx.x >> 5] = s;
    __syncthreads();
    if (threadIdx.x == 0) {
        float t = 0.f;
        #pragma unroll
        for (int i = 0; i < 8; i++) t += red[i];
        g_am[k] = t * (1.f / 512.f);
    }
}

__global__ void k_cheb() {
    __shared__ float adj[144], lap[144], L2s[144], deg[12], dh[12];
    int t = threadIdx.x;
    if (t < 144) adj[t] = fmaxf(g_am[t], 0.f);
    __syncthreads();
    if (t < 12) {
        float s = 0.f;
        #pragma unroll
        for (int j = 0; j < 12; j++) s += adj[t * 12 + j];
        deg[t] = s;
        dh[t] = 1.f / (sqrtf(s) + 1e-7f);
    }
    __syncthreads();
    if (t < 144) {
        int i = t / 12, j = t % 12;
        float as = 0.5f * (adj[i * 12 + j] + adj[j * 12 + i]);
        lap[t] = dh[i] * (((i == j) ? deg[i] : 0.f) - as) * dh[j];
    }
    __syncthreads();
    if (t < 144) {
        int i = t / 12, j = t % 12;
        float s = 0.f;
        #pragma unroll
        for (int k = 0; k < 12; k++) s += lap[i * 12 + k] * lap[k * 12 + j];
        L2s[t] = 2.f * s;
    }
    __syncthreads();
    if (t < 144) {
        int i = t / 12, j = t % 12;
        float s = 0.f;
        #pragma unroll
        for (int k = 0; k < 12; k++) s += lap[i * 12 + k] * L2s[k * 12 + j];
        g_cheb[t]       = 0.f;
        g_cheb[144 + t] = lap[t];
        g_cheb[288 + t] = L2s[t];
        g_cheb[432 + t] = 2.f * s - lap[t];
    }
}

// ============ GCN: cheb mix + bias + relu + residual ([C][N][F]) ============
__global__ void k_gcnpost(const float* __restrict__ Hres, const float* __restrict__ gcnb,
                          float* __restrict__ Hout,
                          __nv_bfloat16* __restrict__ Ohi, __nv_bfloat16* __restrict__ Olo) {
    int blk = blockIdx.x;
    int n = blk >> 2;
    int chunk = blk & 3;
    int w = n & 3;
    int f = chunk * 128 + threadIdx.x;
    __shared__ float s[12][129];
    __shared__ float ch[144];
    for (int i = threadIdx.x; i < 144; i += 128) ch[i] = g_cheb[w * 144 + i];
    #pragma unroll
    for (int j = 0; j < 12; j++)
        s[j][threadIdx.x] = g_supp[((size_t)j * NN + n) * 512 + f];
    __syncthreads();
    float bias = gcnb[f];
    #pragma unroll
    for (int i = 0; i < 12; i++) {
        float acc = bias;
        #pragma unroll
        for (int j = 0; j < 12; j++)
            acc = fmaf(ch[i * 12 + j], s[j][threadIdx.x], acc);
        size_t o = ((size_t)i * NN + n) * 512 + f;
        float hv = fmaxf(acc, 0.f) + Hres[o];
        Hout[o] = hv;
        if (Ohi) split_bf(hv, Ohi[o], Olo[o]);
    }
}

// ================= pool over W + flatten ====================================
__global__ void k_pool() {
    int idx = blockIdx.x * blockDim.x + threadIdx.x;
    if (idx >= BB * CC * FF) return;
    int f = idx & 511;
    int r = idx >> 9;
    int c = r % 12, b = r / 12;
    float s = 0.f;
    #pragma unroll
    for (int w = 0; w < 4; w++) {
        size_t o = ((size_t)c * NN + (b * 4 + w)) * 512 + f;
        s += g_hs[o] + g_h2[o];
    }
    g_pool[idx] = s;
}

// ================= split-K reduce + leaky + BN ==============================
__global__ void k_fcreduce(int S, const float* __restrict__ bias,
                           const float* __restrict__ bng, const float* __restrict__ bnb,
                           const float* __restrict__ bnm, const float* __restrict__ bnv,
                           float* __restrict__ out) {
    int idx = blockIdx.x * blockDim.x + threadIdx.x;
    if (idx >= 512 * 512) return;
    float s = 0.f;
    for (int p = 0; p < S; p++) s += g_fcpart[(size_t)p * 512 * 512 + idx];
    int c = idx & 511;
    s += bias[c];
    s = s > 0.f ? s : 0.01f * s;
    s = (s - bnm[c]) * rsqrtf(bnv[c] + 1e-5f) * bng[c] + bnb[c];
    out[idx] = s;
}

// ================= fc3 (N=4) ================================================
__global__ void k_fc3(const float* __restrict__ w, const float* __restrict__ b,
                      float* __restrict__ out) {
    int bb = blockIdx.x;
    float s0 = 0.f, s1 = 0.f, s2 = 0.f, s3 = 0.f;
    for (int j = threadIdx.x; j < 512; j += 128) {
        float v = g_z2[bb * 512 + j];
        const float* wr = w + j * 4;
        s0 += v * wr[0]; s1 += v * wr[1]; s2 += v * wr[2]; s3 += v * wr[3];
    }
    __shared__ float red[4][4];
    for (int o = 16; o; o >>= 1) {
        s0 += __shfl_down_sync(0xffffffffu, s0, o);
        s1 += __shfl_down_sync(0xffffffffu, s1, o);
        s2 += __shfl_down_sync(0xffffffffu, s2, o);
        s3 += __shfl_down_sync(0xffffffffu, s3, o);
    }
    int wid = threadIdx.x >> 5;
    if ((threadIdx.x & 31) == 0) {
        red[wid][0] = s0; red[wid][1] = s1; red[wid][2] = s2; red[wid][3] = s3;
    }
    __syncthreads();
    if (threadIdx.x < 4) {
        float t = red[0][threadIdx.x] + red[1][threadIdx.x] +
                  red[2][threadIdx.x] + red[3][threadIdx.x];
        out[bb * 4 + threadIdx.x] = t + b[threadIdx.x];
    }
}

// ================= launch ===================================================
extern "C" void kernel_launch(void* const* d_in, const int* in_sizes, int n_in,
                              void* d_out, int out_size) {
    const float* x    = (const float*)d_in[0];
    const float* wih  = (const float*)d_in[1];
    const float* whh  = (const float*)d_in[2];
    const float* bih  = (const float*)d_in[3];
    const float* bhh  = (const float*)d_in[4];
    const float* c0w  = (const float*)d_in[5];
    const float* c0b  = (const float*)d_in[6];
    const float* c1w  = (const float*)d_in[7];
    const float* c1b  = (const float*)d_in[8];
    const float* c2w  = (const float*)d_in[9];
    const float* c2b  = (const float*)d_in[10];
    const float* gcnw = (const float*)d_in[11];
    const float* gcnb = (const float*)d_in[12];
    const float* fc1w = (const float*)d_in[13];
    const float* fc1b = (const float*)d_in[14];
    const float* bn1g = (const float*)d_in[15];
    const float* bn1b = (const float*)d_in[16];
    const float* bn1m = (const float*)d_in[17];
    const float* bn1v = (const float*)d_in[18];
    const float* fc2w = (const float*)d_in[19];
    const float* fc2b = (const float*)d_in[20];
    const float* bn2g = (const float*)d_in[21];
    const float* bn2b = (const float*)d_in[22];
    const float* bn2m = (const float*)d_in[23];
    const float* bn2v = (const float*)d_in[24];
    const float* fc3w = (const float*)d_in[25];
    const float* fc3b = (const float*)d_in[26];
    float* out = (float*)d_out;

    cudaFuncSetAttribute(gemmMMA, cudaFuncAttributeMaxDynamicSharedMemorySize, GEMM_SMEM);

    float *p_xW, *p_hgp, *p_hs, *p_h1, *p_h2, *p_supp, *p_pool, *p_part, *p_z1, *p_z2;
    cudaGetSymbolAddress((void**)&p_xW,  g_xW);
    cudaGetSymbolAddress((void**)&p_hgp, g_hgp);
    cudaGetSymbolAddress((void**)&p_hs,  g_hs);
    cudaGetSymbolAddress((void**)&p_h1,  g_h1);
    cudaGetSymbolAddress((void**)&p_h2,  g_h2);
    cudaGetSymbolAddress((void**)&p_supp, g_supp);
    cudaGetSymbolAddress((void**)&p_pool, g_pool);
    cudaGetSymbolAddress((void**)&p_part, g_fcpart);
    cudaGetSymbolAddress((void**)&p_z1,  g_z1);
    cudaGetSymbolAddress((void**)&p_z2,  g_z2);
    __nv_bfloat16 *p_axh, *p_axl, *p_hbh, *p_hbl, *p_h1bh, *p_h1bl;
    __nv_bfloat16 *p_wihh, *p_wihl, *p_whhh, *p_whhl, *p_g0h, *p_g0l, *p_g1h, *p_g1l;
    cudaGetSymbolAddress((void**)&p_axh,  g_axh);
    cudaGetSymbolAddress((void**)&p_axl,  g_axl);
    cudaGetSymbolAddress((void**)&p_hbh,  g_hbh);
    cudaGetSymbolAddress((void**)&p_hbl,  g_hbl);
    cudaGetSymbolAddress((void**)&p_h1bh, g_h1bh);
    cudaGetSymbolAddress((void**)&p_h1bl, g_h1bl);
    cudaGetSymbolAddress((void**)&p_wihh, g_wihh);
    cudaGetSymbolAddress((void**)&p_wihl, g_wihl);
    cudaGetSymbolAddress((void**)&p_whhh, g_whhh);
    cudaGetSymbolAddress((void**)&p_whhl, g_whhl);
    cudaGetSymbolAddress((void**)&p_g0h,  g_g0h);
    cudaGetSymbolAddress((void**)&p_g0l,  g_g0l);
    cudaGetSymbolAddress((void**)&p_g1h,  g_g1h);
    cudaGetSymbolAddress((void**)&p_g1l,  g_g1l);

    // 0) input-side conversions
    k_cvt_x<<<(MROWS * FF + 255) / 256, 256>>>(x);
    k_cvt<<<(G3 * FF + 255) / 256, 256>>>(wih, p_wihh, p_wihl, G3 * FF);
    k_cvt<<<(G3 * FF + 255) / 256, 256>>>(whh, p_whhh, p_whhl, G3 * FF);

    // 1) input-gate preacts: [24576,1536] = x * wih^T + bih  (HMMA)
    gemmMMA<<<dim3(G3 / 128, MROWS / 128), 256, GEMM_SMEM>>>(
        p_axh, p_axl, p_wihh, p_wihl, bih, p_xW, MROWS, G3, FF, 1);

    // 2) 12 recurrent steps: split-K=2 GEMM (384 blocks -> better SM balance)
    k_gru_gate0<<<(NN * FF + 255) / 256, 256>>>(bhh);
    for (int t = 1; t < CC; t++) {
        gemmMMA<<<dim3(G3 / 128, NN / 128, 2), 256, GEMM_SMEM>>>(
            p_hbh + (size_t)(t - 1) * NN * FF, p_hbl + (size_t)(t - 1) * NN * FF,
            p_whhh, p_whhl, nullptr, p_hgp, NN, G3, FF, 2);
        k_gru_gate<<<(NN * FF + 255) / 256, 256>>>(t, bhh);
    }

    // 3) graph learning -> chebyshev basis (+ GCN weight conversion)
    k_y1<<<(BB * CC * FF + 255) / 256, 256>>>(c0w, c0b);
    k_y2<<<BB * CC, 128>>>(c1w, c1b);
    k_y3mean<<<CC * CC, 256>>>(c2w, c2b);
    k_cheb<<<1, 160>>>();
    k_cvtT<<<(FF * FF + 255) / 256, 256>>>(gcnw, p_g0h, p_g0l);
    k_cvtT<<<(FF * FF + 255) / 256, 256>>>(gcnw + FF * FF, p_g1h, p_g1l);

    // 4) GCN layer 0
    gemmMMA<<<dim3(FF / 128, MROWS / 128), 256, GEMM_SMEM>>>(
        p_hbh, p_hbl, p_g0h, p_g0l, nullptr, p_supp, MROWS, FF, FF, 1);
    k_gcnpost<<<NN * 4, 128>>>(p_hs, gcnb, p_h1, p_h1bh, p_h1bl);

    // 5) GCN layer 1
    gemmMMA<<<dim3(FF / 128, MROWS / 128), 256, GEMM_SMEM>>>(
        p_h1bh, p_h1bl, p_g1h, p_g1l, nullptr, p_supp, MROWS, FF, FF, 1);
    k_gcnpost<<<NN * 4, 128>>>(p_h1, gcnb + FF, p_h2, nullptr, nullptr);

    // 6) pool over W -> [B, C*F]
    k_pool<<<(BB * CC * FF + 255) / 256, 256>>>();

    // 7) classifier head (fp32 split-K)
    gemm128<false, 0, 0><<<dim3(4, 4, 8), 256>>>(
        p_pool, fc1w, nullptr, p_part, BB, 512, CC * FF, 768);
    k_fcreduce<<<1024, 256>>>(8, fc1b, bn1g, bn1b, bn1m, bn1v, p_z1);
    gemm128<false, 0, 0><<<dim3(4, 4, 4), 256>>>(
        p_z1, fc2w, nullptr, p_part, BB, 512, 512, 128);
    k_fcreduce<<<1024, 256>>>(4, fc2b, bn2g, bn2b, bn2m, bn2v, p_z2);
    k_fc3<<<BB, 128>>>(fc3w, fc3b, out);
}

// round 12
// speedup vs baseline: 1.1645x; 1.0017x over previous
#include <cuda_runtime.h>
#include <cuda_bf16.h>
#include <math.h>
#include <cstdint>

#define BB 512
#define CC 12
#define WW 4
#define FF 512
#define NN 2048      // B*W
#define G3 1536      // 3*F
#define MROWS 24576  // C*N rows

// ---------------- scratch (device globals; no allocation allowed) ----------
__device__ float g_xW [MROWS * G3];    // [C][N][3F] input gate preacts
__device__ float g_hgp[3 * NN * G3];   // split-K partials for recurrent GEMM
__device__ float g_hs [CC * NN * FF];  // [C][N][F]  h after each step
__device__ float g_y1 [BB * CC * FF];
__device__ float g_y2 [BB * CC];
__device__ float g_am [CC * CC];
__device__ float g_cheb[4 * CC * CC];
__device__ float g_h1 [MROWS * FF];    // [C][N][F]
__device__ float g_h2 [MROWS * FF];
__device__ float g_supp[MROWS * FF];
__device__ float g_pool[BB * CC * FF]; // [B, C*F]
__device__ float g_fcpart[8 * 512 * 512];
__device__ float g_z1 [BB * 512];
__device__ float g_z2 [BB * 512];
// bf16 hi/lo planes for tensor-core GEMMs
__device__ __nv_bfloat16 g_axh [MROWS * FF], g_axl [MROWS * FF];   // gathered x
__device__ __nv_bfloat16 g_hbh [CC * NN * FF], g_hbl [CC * NN * FF]; // GRU h
__device__ __nv_bfloat16 g_h1bh[MROWS * FF], g_h1bl[MROWS * FF];   // GCN h1
__device__ __nv_bfloat16 g_wihh[G3 * FF], g_wihl[G3 * FF];
__device__ __nv_bfloat16 g_whhh[G3 * FF], g_whhl[G3 * FF];
__device__ __nv_bfloat16 g_g0h [FF * FF], g_g0l [FF * FF];         // gcnw0^T [N,K]
__device__ __nv_bfloat16 g_g1h [FF * FF], g_g1l [FF * FF];         // gcnw1^T [N,K]

#define BKP 40                      // padded k-stride (80B rows: 16B-aligned, conflict-free)

__device__ __forceinline__ void mma16816(float* d, const uint32_t* a, const uint32_t* b) {
    asm volatile(
        "mma.sync.aligned.m16n8k16.row.col.f32.bf16.bf16.f32 "
        "{%0,%1,%2,%3}, {%4,%5,%6,%7}, {%8,%9}, {%0,%1,%2,%3};\n"
        : "+f"(d[0]), "+f"(d[1]), "+f"(d[2]), "+f"(d[3])
        : "r"(a[0]), "r"(a[1]), "r"(a[2]), "r"(a[3]), "r"(b[0]), "r"(b[1]));
}
__device__ __forceinline__ void ldm_x4(uint32_t* r, uint32_t addr) {
    asm volatile("ldmatrix.sync.aligned.m8n8.x4.shared.b16 {%0,%1,%2,%3}, [%4];"
        : "=r"(r[0]), "=r"(r[1]), "=r"(r[2]), "=r"(r[3]) : "r"(addr));
}
__device__ __forceinline__ void split_bf(float v, __nv_bfloat16& h, __nv_bfloat16& l) {
    h = __float2bfloat16(v);
    l = __float2bfloat16(v - __bfloat162float(h));
}

// ================= HMMA bf16 hi/lo split GEMM (fused 3-combo) ===============
// D[M,N] fp32 = (Ah+Al)*(Bh+Bl)^T - Al*Bl^T  (lo*lo dropped)
// kSplit>1: grid.z splits the K chunk range (uneven allowed); partial z -> C + z*M*N.
#define MATE (128 * BKP)            // 5120 elems per matrix tile
#define STAGE4 (4 * MATE)           // Ah|Al|Bh|Bl
#define GEMM_SMEM (2 * STAGE4 * 2)  // 81920 bytes (2 stages)

__global__ void __launch_bounds__(256, 2)
gemmMMA(const __nv_bfloat16* __restrict__ Ah, const __nv_bfloat16* __restrict__ Al,
        const __nv_bfloat16* __restrict__ Bh, const __nv_bfloat16* __restrict__ Bl,
        const float* __restrict__ bias, float* __restrict__ C, int M, int N, int K,
        int kSplit)
{
    extern __shared__ __align__(16) __nv_bfloat16 dyn[];
    const uint32_t Su32 = (uint32_t)__cvta_generic_to_shared(dyn);

    const int tid = threadIdx.x, wid = tid >> 5, lane = tid & 31;
    const int wm = wid & 3, wn = wid >> 2;
    const int bm = blockIdx.y * 128, bn = blockIdx.x * 128;
    const int r = lane >> 2, cq = lane & 3;

    const __nv_bfloat16* mat[4] = {
        Ah + (size_t)bm * K, Al + (size_t)bm * K,
        Bh + (size_t)bn * K, Bl + (size_t)bn * K };
    const int KCH = K >> 5;
    // uneven split: first (KCH % kSplit) z-blocks get one extra chunk
    const int cps = KCH / kSplit, rem = KCH % kSplit;
    const int z = blockIdx.z;
    const int c0 = z * cps + (z < rem ? z : rem);
    const int c1 = c0 + cps + (z < rem ? 1 : 0);
    C += (size_t)z * M * N;

    float acc[2][8][4];
    #pragma unroll
    for (int mi = 0; mi < 2; mi++)
        #pragma unroll
        for (int ni = 0; ni < 8; ni++)
            #pragma unroll
            for (int q = 0; q < 4; q++) acc[mi][ni][q] = 0.f;

    const int prow = tid >> 2, pc4 = (tid & 3) * 8;
    auto prefetch = [&](int c) {
        const int k0 = c << 5, st = c & 1;
        #pragma unroll
        for (int m = 0; m < 4; m++) {
            #pragma unroll
            for (int i = 0; i < 2; i++) {
                const int row = prow + i * 64;
                const uint32_t soff = (uint32_t)(st * STAGE4 + m * MATE + row * BKP + pc4) * 2;
                const __nv_bfloat16* src = mat[m] + (size_t)row * K + k0 + pc4;
                asm volatile("cp.async.cg.shared.global [%0], [%1], 16;"
                             :: "r"(Su32 + soff), "l"(src) : "memory");
            }
        }
        asm volatile("cp.async.commit_group;" ::: "memory");
    };

    prefetch(c0);
    if (c0 + 1 < c1) prefetch(c0 + 1);
    for (int c = c0; c < c1; c++) {
        if (c + 1 < c1) asm volatile("cp.async.wait_group 1;" ::: "memory");
        else            asm volatile("cp.async.wait_group 0;" ::: "memory");
        __syncthreads();

        const uint32_t S = Su32 + (uint32_t)((c & 1) * STAGE4) * 2;
        const uint32_t SAh = S, SAl = S + MATE * 2, SBh = S + 2 * MATE * 2, SBl = S + 3 * MATE * 2;
        #pragma unroll
        for (int ks = 0; ks < 2; ks++) {
            const int k0 = ks * 16;
            const uint32_t aoff = (uint32_t)((wm * 32 + (lane & 15)) * BKP +
                                             k0 + ((lane >> 4) << 3)) * 2;
            const uint32_t boffbase = (uint32_t)((wn * 64 + ((lane >> 4) << 3) + (lane & 7)) * BKP +
                                                 k0 + (((lane >> 3) & 1) << 3)) * 2;
            uint32_t ah[2][4], al[2][4], bf[8][2];
            #pragma unroll
            for (int mi = 0; mi < 2; mi++) ldm_x4(ah[mi], SAh + aoff + mi * 16 * BKP * 2);
            #pragma unroll
            for (int nj = 0; nj < 4; nj++) {
                uint32_t q[4];
                ldm_x4(q, SBh + boffbase + nj * 16 * BKP * 2);
                bf[2 * nj][0] = q[0]; bf[2 * nj][1] = q[1];
                bf[2 * nj + 1][0] = q[2]; bf[2 * nj + 1][1] = q[3];
            }
            #pragma unroll
            for (int mi = 0; mi < 2; mi++)
                #pragma unroll
                for (int ni = 0; ni < 8; ni++)
                    mma16816(acc[mi][ni], ah[mi], bf[ni]);
            #pragma unroll
            for (int mi = 0; mi < 2; mi++) ldm_x4(al[mi], SAl + aoff + mi * 16 * BKP * 2);
            #pragma unroll
            for (int mi = 0; mi < 2; mi++)
                #pragma unroll
                for (int ni = 0; ni < 8; ni++)
                    mma16816(acc[mi][ni], al[mi], bf[ni]);
            #pragma unroll
            for (int nj = 0; nj < 4; nj++) {
                uint32_t q[4];
                ldm_x4(q, SBl + boffbase + nj * 16 * BKP * 2);
                bf[2 * nj][0] = q[0]; bf[2 * nj][1] = q[1];
                bf[2 * nj + 1][0] = q[2]; bf[2 * nj + 1][1] = q[3];
            }
            #pragma unroll
            for (int mi = 0; mi < 2; mi++)
                #pragma unroll
                for (int ni = 0; ni < 8; ni++)
                    mma16816(acc[mi][ni], ah[mi], bf[ni]);
        }
        __syncthreads();
        if (c + 2 < c1) prefetch(c + 2);
    }

    #pragma unroll
    for (int mi = 0; mi < 2; mi++) {
        const int row0 = bm + wm * 32 + mi * 16 + r;
        #pragma unroll
        for (int ni = 0; ni < 8; ni++) {
            const int col = bn + wn * 64 + ni * 8 + cq * 2;
            float b0 = 0.f, b1 = 0.f;
            if (bias) { b0 = bias[col]; b1 = bias[col + 1]; }
            float2 v0 = make_float2(acc[mi][ni][0] + b0, acc[mi][ni][1] + b1);
            float2 v1 = make_float2(acc[mi][ni][2] + b0, acc[mi][ni][3] + b1);
            *(float2*)&C[(size_t)row0 * N + col] = v0;
            *(float2*)&C[(size_t)(row0 + 8) * N + col] = v1;
        }
    }
}

// ================= fp32 128x128 GEMM (head only) ============================
template<bool TRANSB, int AMAP, int EPI>
__global__ void __launch_bounds__(256, 2)
gemm128(const float* __restrict__ A, const float* __restrict__ B,
        const float* __restrict__ bias, float* __restrict__ C,
        int M, int N, int K, int kChunk)
{
    __shared__ float As[16][132];
    __shared__ float Bs[16][132];
    const int tid = threadIdx.x;
    const int tx = tid & 15, ty = tid >> 4;
    const int bm = blockIdx.y * 128, bn = blockIdx.x * 128;
    int ks = 0, ke = K;
    if (kChunk > 0) {
        ks = blockIdx.z * kChunk; ke = ks + kChunk;
        C += (size_t)blockIdx.z * M * N;
    }
    const int lr = tid >> 2;
    const int lc = (tid & 3) * 4;
    const int bR = tid >> 5;
    const int bC = (tid & 31) * 4;
    size_t aRow0 = (size_t)(bm + lr), aRow1 = (size_t)(bm + lr + 64);

    float4 pa0, pa1, pb0, pb1;
    auto loadg = [&](int k0) {
        pa0 = *(const float4*)&A[aRow0 * K + k0 + lc];
        pa1 = *(const float4*)&A[aRow1 * K + k0 + lc];
        if (TRANSB) {
            pb0 = *(const float4*)&B[(size_t)(bn + lr) * K + k0 + lc];
            pb1 = *(const float4*)&B[(size_t)(bn + lr + 64) * K + k0 + lc];
        } else {
            pb0 = *(const float4*)&B[(size_t)(k0 + bR) * N + bn + bC];
            pb1 = *(const float4*)&B[(size_t)(k0 + bR + 8) * N + bn + bC];
        }
    };
    unsigned long long acc[8][4];
    #pragma unroll
    for (int i = 0; i < 8; i++)
        #pragma unroll
        for (int j = 0; j < 4; j++) acc[i][j] = 0ULL;
    loadg(ks);
    for (int k0 = ks; k0 < ke; k0 += 16) {
        As[lc + 0][lr] = pa0.x; As[lc + 1][lr] = pa0.y;
        As[lc + 2][lr] = pa0.z; As[lc + 3][lr] = pa0.w;
        As[lc + 0][lr + 64] = pa1.x; As[lc + 1][lr + 64] = pa1.y;
        As[lc + 2][lr + 64] = pa1.z; As[lc + 3][lr + 64] = pa1.w;
        if (TRANSB) {
            Bs[lc + 0][lr] = pb0.x; Bs[lc + 1][lr] = pb0.y;
            Bs[lc + 2][lr] = pb0.z; Bs[lc + 3][lr] = pb0.w;
            Bs[lc + 0][lr + 64] = pb1.x; Bs[lc + 1][lr + 64] = pb1.y;
            Bs[lc + 2][lr + 64] = pb1.z; Bs[lc + 3][lr + 64] = pb1.w;
        } else {
            *(float4*)&Bs[bR][bC]     = pb0;
            *(float4*)&Bs[bR + 8][bC] = pb1;
        }
        __syncthreads();
        if (k0 + 16 < ke) loadg(k0 + 16);
        #pragma unroll
        for (int k = 0; k < 16; k++) {
            float4 a0 = *(const float4*)&As[k][ty * 4];
            float4 a1 = *(const float4*)&As[k][64 + ty * 4];
            ulonglong2 b0 = *(const ulonglong2*)&Bs[k][tx * 4];
            ulonglong2 b1 = *(const ulonglong2*)&Bs[k][64 + tx * 4];
            float ar[8] = {a0.x, a0.y, a0.z, a0.w, a1.x, a1.y, a1.z, a1.w};
            unsigned long long bp[4] = {b0.x, b0.y, b1.x, b1.y};
            #pragma unroll
            for (int i = 0; i < 8; i++) {
                unsigned long long ad;
                asm("mov.b64 %0, {%1, %1};" : "=l"(ad) : "f"(ar[i]));
                #pragma unroll
                for (int j = 0; j < 4; j++)
                    asm("fma.rn.f32x2 %0, %1, %2, %0;"
                        : "+l"(acc[i][j]) : "l"(ad), "l"(bp[j]));
            }
        }
        __syncthreads();
    }
    #pragma unroll
    for (int i = 0; i < 8; i++) {
        int gm = bm + ((i < 4) ? (ty * 4 + i) : (60 + ty * 4 + i));
        float v[8];
        #pragma unroll
        for (int j = 0; j < 4; j++)
            asm("mov.b64 {%0, %1}, %2;"
                : "=f"(v[2 * j]), "=f"(v[2 * j + 1]) : "l"(acc[i][j]));
        #pragma unroll
        for (int h = 0; h < 2; h++) {
            int gn = bn + (h ? 64 + tx * 4 : tx * 4);
            float t0 = v[h * 4], t1 = v[h * 4 + 1], t2 = v[h * 4 + 2], t3 = v[h * 4 + 3];
            if (EPI >= 1) {
                t0 += bias[gn + 0]; t1 += bias[gn + 1];
                t2 += bias[gn + 2]; t3 += bias[gn + 3];
            }
            float4 o; o.x = t0; o.y = t1; o.z = t2; o.w = t3;
            *(float4*)&C[(size_t)gm * N + gn] = o;
        }
    }
}

// ================= conversions =============================================
__global__ void k_cvt(const float* __restrict__ src, __nv_bfloat16* __restrict__ hi,
                      __nv_bfloat16* __restrict__ lo, int n) {
    int i = blockIdx.x * blockDim.x + threadIdx.x;
    if (i >= n) return;
    split_bf(src[i], hi[i], lo[i]);
}

// gcn weight [K,N] -> planes [N,K]
__global__ void k_cvtT(const float* __restrict__ W, __nv_bfloat16* __restrict__ hi,
                       __nv_bfloat16* __restrict__ lo) {
    int i = blockIdx.x * blockDim.x + threadIdx.x;
    if (i >= FF * FF) return;
    int n = i >> 9, k = i & 511;
    split_bf(W[k * FF + n], hi[i], lo[i]);
}

// gather x -> A planes [C][N][F]
__global__ void k_cvt_x(const float* __restrict__ x) {
    int idx = blockIdx.x * blockDim.x + threadIdx.x;
    if (idx >= MROWS * FF) return;
    int f = idx & 511;
    int r = idx >> 9;
    int t = r / NN, n = r - t * NN;
    int b = n >> 2, w = n & 3;
    float v = x[(((size_t)b * CC + t) * WW + w) * FF + f];
    split_bf(v, g_axh[idx], g_axl[idx]);
}

// ================= GRU gates (vectorized float4) ============================
__device__ __forceinline__ void gate_store4(size_t o, const float* h) {
    *(float4*)&g_hs[o] = make_float4(h[0], h[1], h[2], h[3]);
    __align__(8) __nv_bfloat16 hh[4], hl[4];
    #pragma unroll
    for (int i = 0; i < 4; i++) split_bf(h[i], hh[i], hl[i]);
    *(uint2*)&g_hbh[o] = *(uint2*)hh;
    *(uint2*)&g_hbl[o] = *(uint2*)hl;
}

__global__ void k_gru_gate0(const float* __restrict__ bhh) {
    int idx = blockIdx.x * blockDim.x + threadIdx.x;
    if (idx >= NN * FF / 4) return;
    int n = idx >> 7, f = (idx & 127) * 4;
    const float* xw = g_xW + (size_t)n * G3;
    float4 xr = *(const float4*)&xw[f];
    float4 xz = *(const float4*)&xw[512 + f];
    float4 xn = *(const float4*)&xw[1024 + f];
    float4 br = *(const float4*)&bhh[f];
    float4 bz = *(const float4*)&bhh[512 + f];
    float4 bn = *(const float4*)&bhh[1024 + f];
    float h[4];
    #pragma unroll
    for (int i = 0; i < 4; i++) {
        float xri = ((const float*)&xr)[i] + ((const float*)&br)[i];
        float xzi = ((const float*)&xz)[i] + ((const float*)&bz)[i];
        float xni = ((const float*)&xn)[i];
        float bni = ((const float*)&bn)[i];
        float r = 1.f / (1.f + expf(-xri));
        float z = 1.f / (1.f + expf(-xzi));
        float nv = tanhf(xni + r * bni);
        h[i] = (1.f - z) * nv;
    }
    gate_store4((size_t)n * FF + f, h);
}

// t>0: sums the three split-K partials of h_prev @ whh^T, adds bhh, gate math.
__global__ void k_gru_gate(int t, const float* __restrict__ bhh) {
    int idx = blockIdx.x * blockDim.x + threadIdx.x;
    if (idx >= NN * FF / 4) return;
    int n = idx >> 7, f = (idx & 127) * 4;
    const size_t base = (size_t)n * G3;
    const float* p0 = g_hgp + base;
    const float* p1 = g_hgp + (size_t)NN * G3 + base;
    const float* p2 = g_hgp + (size_t)2 * NN * G3 + base;
    float hr[4], hz[4], hn[4];
    #pragma unroll
    for (int g = 0; g < 3; g++) {
        float* dst = (g == 0) ? hr : (g == 1) ? hz : hn;
        const int off = g * 512 + f;
        float4 a = *(const float4*)&p0[off];
        float4 b = *(const float4*)&p1[off];
        float4 c = *(const float4*)&p2[off];
        float4 d = *(const float4*)&bhh[off];
        dst[0] = a.x + b.x + c.x + d.x;
        dst[1] = a.y + b.y + c.y + d.y;
        dst[2] = a.z + b.z + c.z + d.z;
        dst[3] = a.w + b.w + c.w + d.w;
    }
    const float* xw = g_xW + ((size_t)t * NN + n) * G3;
    float4 xr = *(const float4*)&xw[f];
    float4 xz = *(const float4*)&xw[512 + f];
    float4 xn = *(const float4*)&xw[1024 + f];
    float4 hp = *(const float4*)&g_hs[((size_t)(t - 1) * NN + n) * FF + f];
    float h[4];
    #pragma unroll
    for (int i = 0; i < 4; i++) {
        float r = 1.f / (1.f + expf(-(((const float*)&xr)[i] + hr[i])));
        float z = 1.f / (1.f + expf(-(((const float*)&xz)[i] + hz[i])));
        float nv = tanhf(((const float*)&xn)[i] + r * hn[i]);
        h[i] = (1.f - z) * nv + z * ((const float*)&hp)[i];
    }
    gate_store4(((size_t)t * NN + n) * FF + f, h);
}

// ================= graph learning ==========================================
__global__ void k_y1(const float* __restrict__ w, const float* __restrict__ b0) {
    int idx = blockIdx.x * blockDim.x + threadIdx.x;
    if (idx >= BB * CC * FF) return;
    int f = idx & 511;
    int r = idx >> 9;
    int c = r % 12, b = r / 12;
    float s = b0[0];
    #pragma unroll
    for (int wi = 0; wi < 4; wi++)
        s += g_hs[((size_t)c * NN + (b * 4 + wi)) * FF + f] * w[wi];
    g_y1[idx] = fmaxf(s, 0.f);
}

__global__ void k_y2(const float* __restrict__ w, const float* __restrict__ b1) {
    int r = blockIdx.x;
    float s = 0.f;
    for (int f = threadIdx.x; f < 512; f += 128)
        s += g_y1[(size_t)r * 512 + f] * w[f];
    __shared__ float red[4];
    for (int o = 16; o; o >>= 1) s += __shfl_down_sync(0xffffffffu, s, o);
    if ((threadIdx.x & 31) == 0) red[threadIdx.x >> 5] = s;
    __syncthreads();
    if (threadIdx.x == 0)
        g_y2[r] = fmaxf(red[0] + red[1] + red[2] + red[3] + b1[0], 0.f);
}

__global__ void k_y3mean(const float* __restrict__ w2, const float* __restrict__ b2) {
    int k = blockIdx.x;
    float wl[12];
    #pragma unroll
    for (int c = 0; c < 12; c++) wl[c] = w2[k * 12 + c];
    float bk = b2[k];
    float s = 0.f;
    for (int b = threadIdx.x; b < 512; b += 256) {
        float v = bk;
        #pragma unroll
        for (int c = 0; c < 12; c++) v += g_y2[b * 12 + c] * wl[c];
        s += fmaxf(v, 0.f);
    }
    __shared__ float red[8];
    for (int o = 16; o; o >>= 1) s += __shfl_down_sync(0xffffffffu, s, o);
    if ((threadIdx.x & 31) == 0) red[threadIdx.x >> 5] = s;
    __syncthreads();
    if (threadIdx.x == 0) {
        float t = 0.f;
        #pragma unroll
        for (int i = 0; i < 8; i++) t += red[i];
        g_am[k] = t * (1.f / 512.f);
    }
}

__global__ void k_cheb() {
    __shared__ float adj[144], lap[144], L2s[144], deg[12], dh[12];
    int t = threadIdx.x;
    if (t < 144) adj[t] = fmaxf(g_am[t], 0.f);
    __syncthreads();
    if (t < 12) {
        float s = 0.f;
        #pragma unroll
        for (int j = 0; j < 12; j++) s += adj[t * 12 + j];
        deg[t] = s;
        dh[t] = 1.f / (sqrtf(s) + 1e-7f);
    }
    __syncthreads();
    if (t < 144) {
        int i = t / 12, j = t % 12;
        float as = 0.5f * (adj[i * 12 + j] + adj[j * 12 + i]);
        lap[t] = dh[i] * (((i == j) ? deg[i] : 0.f) - as) * dh[j];
    }
    __syncthreads();
    if (t < 144) {
        int i = t / 12, j = t % 12;
        float s = 0.f;
        #pragma unroll
        for (int k = 0; k < 12; k++) s += lap[i * 12 + k] * lap[k * 12 + j];
        L2s[t] = 2.f * s;
    }
    __syncthreads();
    if (t < 144) {
        int i = t / 12, j = t % 12;
        float s = 0.f;
        #pragma unroll
        for (int k = 0; k < 12; k++) s += lap[i * 12 + k] * L2s[k * 12 + j];
        g_cheb[t]       = 0.f;
        g_cheb[144 + t] = lap[t];
        g_cheb[288 + t] = L2s[t];
        g_cheb[432 + t] = 2.f * s - lap[t];
    }
}

// ============ GCN: cheb mix + bias + relu + residual ([C][N][F]) ============
__global__ void k_gcnpost(const float* __restrict__ Hres, const float* __restrict__ gcnb,
                          float* __restrict__ Hout,
                          __nv_bfloat16* __restrict__ Ohi, __nv_bfloat16* __restrict__ Olo) {
    int blk = blockIdx.x;
    int n = blk >> 2;
    int chunk = blk & 3;
    int w = n & 3;
    int f = chunk * 128 + threadIdx.x;
    __shared__ float s[12][129];
    __shared__ float ch[144];
    for (int i = threadIdx.x; i < 144; i += 128) ch[i] = g_cheb[w * 144 + i];
    #pragma unroll
    for (int j = 0; j < 12; j++)
        s[j][threadIdx.x] = g_supp[((size_t)j * NN + n) * 512 + f];
    __syncthreads();
    float bias = gcnb[f];
    #pragma unroll
    for (int i = 0; i < 12; i++) {
        float acc = bias;
        #pragma unroll
        for (int j = 0; j < 12; j++)
            acc = fmaf(ch[i * 12 + j], s[j][threadIdx.x], acc);
        size_t o = ((size_t)i * NN + n) * 512 + f;
        float hv = fmaxf(acc, 0.f) + Hres[o];
        Hout[o] = hv;
        if (Ohi) split_bf(hv, Ohi[o], Olo[o]);
    }
}

// ================= pool over W + flatten ====================================
__global__ void k_pool() {
    int idx = blockIdx.x * blockDim.x + threadIdx.x;
    if (idx >= BB * CC * FF) return;
    int f = idx & 511;
    int r = idx >> 9;
    int c = r % 12, b = r / 12;
    float s = 0.f;
    #pragma unroll
    for (int w = 0; w < 4; w++) {
        size_t o = ((size_t)c * NN + (b * 4 + w)) * 512 + f;
        s += g_hs[o] + g_h2[o];
    }
    g_pool[idx] = s;
}

// ================= split-K reduce + leaky + BN ==============================
__global__ void k_fcreduce(int S, const float* __restrict__ bias,
                           const float* __restrict__ bng, const float* __restrict__ bnb,
                           const float* __restrict__ bnm, const float* __restrict__ bnv,
                           float* __restrict__ out) {
    int idx = blockIdx.x * blockDim.x + threadIdx.x;
    if (idx >= 512 * 512) return;
    float s = 0.f;
    for (int p = 0; p < S; p++) s += g_fcpart[(size_t)p * 512 * 512 + idx];
    int c = idx & 511;
    s += bias[c];
    s = s > 0.f ? s : 0.01f * s;
    s = (s - bnm[c]) * rsqrtf(bnv[c] + 1e-5f) * bng[c] + bnb[c];
    out[idx] = s;
}

// ================= fc3 (N=4) ================================================
__global__ void k_fc3(const float* __restrict__ w, const float* __restrict__ b,
                      float* __restrict__ out) {
    int bb = blockIdx.x;
    float s0 = 0.f, s1 = 0.f, s2 = 0.f, s3 = 0.f;
    for (int j = threadIdx.x; j < 512; j += 128) {
        float v = g_z2[bb * 512 + j];
        const float* wr = w + j * 4;
        s0 += v * wr[0]; s1 += v * wr[1]; s2 += v * wr[2]; s3 += v * wr[3];
    }
    __shared__ float red[4][4];
    for (int o = 16; o; o >>= 1) {
        s0 += __shfl_down_sync(0xffffffffu, s0, o);
        s1 += __shfl_down_sync(0xffffffffu, s1, o);
        s2 += __shfl_down_sync(0xffffffffu, s2, o);
        s3 += __shfl_down_sync(0xffffffffu, s3, o);
    }
    int wid = threadIdx.x >> 5;
    if ((threadIdx.x & 31) == 0) {
        red[wid][0] = s0; red[wid][1] = s1; red[wid][2] = s2; red[wid][3] = s3;
    }
    __syncthreads();
    if (threadIdx.x < 4) {
        float t = red[0][threadIdx.x] + red[1][threadIdx.x] +
                  red[2][threadIdx.x] + red[3][threadIdx.x];
        out[bb * 4 + threadIdx.x] = t + b[threadIdx.x];
    }
}

// ================= launch ===================================================
extern "C" void kernel_launch(void* const* d_in, const int* in_sizes, int n_in,
                              void* d_out, int out_size) {
    const float* x    = (const float*)d_in[0];
    const float* wih  = (const float*)d_in[1];
    const float* whh  = (const float*)d_in[2];
    const float* bih  = (const float*)d_in[3];
    const float* bhh  = (const float*)d_in[4];
    const float* c0w  = (const float*)d_in[5];
    const float* c0b  = (const float*)d_in[6];
    const float* c1w  = (const float*)d_in[7];
    const float* c1b  = (const float*)d_in[8];
    const float* c2w  = (const float*)d_in[9];
    const float* c2b  = (const float*)d_in[10];
    const float* gcnw = (const float*)d_in[11];
    const float* gcnb = (const float*)d_in[12];
    const float* fc1w = (const float*)d_in[13];
    const float* fc1b = (const float*)d_in[14];
    const float* bn1g = (const float*)d_in[15];
    const float* bn1b = (const float*)d_in[16];
    const float* bn1m = (const float*)d_in[17];
    const float* bn1v = (const float*)d_in[18];
    const float* fc2w = (const float*)d_in[19];
    const float* fc2b = (const float*)d_in[20];
    const float* bn2g = (const float*)d_in[21];
    const float* bn2b = (const float*)d_in[22];
    const float* bn2m = (const float*)d_in[23];
    const float* bn2v = (const float*)d_in[24];
    const float* fc3w = (const float*)d_in[25];
    const float* fc3b = (const float*)d_in[26];
    float* out = (float*)d_out;

    cudaFuncSetAttribute(gemmMMA, cudaFuncAttributeMaxDynamicSharedMemorySize, GEMM_SMEM);

    float *p_xW, *p_hgp, *p_hs, *p_h1, *p_h2, *p_supp, *p_pool, *p_part, *p_z1, *p_z2;
    cudaGetSymbolAddress((void**)&p_xW,  g_xW);
    cudaGetSymbolAddress((void**)&p_hgp, g_hgp);
    cudaGetSymbolAddress((void**)&p_hs,  g_hs);
    cudaGetSymbolAddress((void**)&p_h1,  g_h1);
    cudaGetSymbolAddress((void**)&p_h2,  g_h2);
    cudaGetSymbolAddress((void**)&p_supp, g_supp);
    cudaGetSymbolAddress((void**)&p_pool, g_pool);
    cudaGetSymbolAddress((void**)&p_part, g_fcpart);
    cudaGetSymbolAddress((void**)&p_z1,  g_z1);
    cudaGetSymbolAddress((void**)&p_z2,  g_z2);
    __nv_bfloat16 *p_axh, *p_axl, *p_hbh, *p_hbl, *p_h1bh, *p_h1bl;
    __nv_bfloat16 *p_wihh, *p_wihl, *p_whhh, *p_whhl, *p_g0h, *p_g0l, *p_g1h, *p_g1l;
    cudaGetSymbolAddress((void**)&p_axh,  g_axh);
    cudaGetSymbolAddress((void**)&p_axl,  g_axl);
    cudaGetSymbolAddress((void**)&p_hbh,  g_hbh);
    cudaGetSymbolAddress((void**)&p_hbl,  g_hbl);
    cudaGetSymbolAddress((void**)&p_h1bh, g_h1bh);
    cudaGetSymbolAddress((void**)&p_h1bl, g_h1bl);
    cudaGetSymbolAddress((void**)&p_wihh, g_wihh);
    cudaGetSymbolAddress((void**)&p_wihl, g_wihl);
    cudaGetSymbolAddress((void**)&p_whhh, g_whhh);
    cudaGetSymbolAddress((void**)&p_whhl, g_whhl);
    cudaGetSymbolAddress((void**)&p_g0h,  g_g0h);
    cudaGetSymbolAddress((void**)&p_g0l,  g_g0l);
    cudaGetSymbolAddress((void**)&p_g1h,  g_g1h);
    cudaGetSymbolAddress((void**)&p_g1l,  g_g1l);

    // 0) input-side conversions
    k_cvt_x<<<(MROWS * FF + 255) / 256, 256>>>(x);
    k_cvt<<<(G3 * FF + 255) / 256, 256>>>(wih, p_wihh, p_wihl, G3 * FF);
    k_cvt<<<(G3 * FF + 255) / 256, 256>>>(whh, p_whhh, p_whhl, G3 * FF);

    // 1) input-gate preacts: [24576,1536] = x * wih^T + bih  (HMMA)
    gemmMMA<<<dim3(G3 / 128, MROWS / 128), 256, GEMM_SMEM>>>(
        p_axh, p_axl, p_wihh, p_wihl, bih, p_xW, MROWS, G3, FF, 1);

    // 2) 12 recurrent steps: split-K=3 GEMM (576 blocks -> ~2 waves of 1/3-K)
    k_gru_gate0<<<(NN * FF / 4 + 255) / 256, 256>>>(bhh);
    for (int t = 1; t < CC; t++) {
        gemmMMA<<<dim3(G3 / 128, NN / 128, 3), 256, GEMM_SMEM>>>(
            p_hbh + (size_t)(t - 1) * NN * FF, p_hbl + (size_t)(t - 1) * NN * FF,
            p_whhh, p_whhl, nullptr, p_hgp, NN, G3, FF, 3);
        k_gru_gate<<<(NN * FF / 4 + 255) / 256, 256>>>(t, bhh);
    }

    // 3) graph learning -> chebyshev basis (+ GCN weight conversion)
    k_y1<<<(BB * CC * FF + 255) / 256, 256>>>(c0w, c0b);
    k_y2<<<BB * CC, 128>>>(c1w, c1b);
    k_y3mean<<<CC * CC, 256>>>(c2w, c2b);
    k_cheb<<<1, 160>>>();
    k_cvtT<<<(FF * FF + 255) / 256, 256>>>(gcnw, p_g0h, p_g0l);
    k_cvtT<<<(FF * FF + 255) / 256, 256>>>(gcnw + FF * FF, p_g1h, p_g1l);

    // 4) GCN layer 0
    gemmMMA<<<dim3(FF / 128, MROWS / 128), 256, GEMM_SMEM>>>(
        p_hbh, p_hbl, p_g0h, p_g0l, nullptr, p_supp, MROWS, FF, FF, 1);
    k_gcnpost<<<NN * 4, 128>>>(p_hs, gcnb, p_h1, p_h1bh, p_h1bl);

    // 5) GCN layer 1
    gemmMMA<<<dim3(FF / 128, MROWS / 128), 256, GEMM_SMEM>>>(
        p_h1bh, p_h1bl, p_g1h, p_g1l, nullptr, p_supp, MROWS, FF, FF, 1);
    k_gcnpost<<<NN * 4, 128>>>(p_h1, gcnb + FF, p_h2, nullptr, nullptr);

    // 6) pool over W -> [B, C*F]
    k_pool<<<(BB * CC * FF + 255) / 256, 256>>>();

    // 7) classifier head (fp32 split-K)
    gemm128<false, 0, 0><<<dim3(4, 4, 8), 256>>>(
        p_pool, fc1w, nullptr, p_part, BB, 512, CC * FF, 768);
    k_fcreduce<<<1024, 256>>>(8, fc1b, bn1g, bn1b, bn1m, bn1v, p_z1);
    gemm128<false, 0, 0><<<dim3(4, 4, 4), 256>>>(
        p_z1, fc2w, nullptr, p_part, BB, 512, 512, 128);
    k_fcreduce<<<1024, 256>>>(4, fc2b, bn2g, bn2b, bn2m, bn2v, p_z2);
    k_fc3<<<BB, 128>>>(fc3w, fc3b, out);
}

// round 13
// speedup vs baseline: 1.2010x; 1.0313x over previous
#include <cuda_runtime.h>
#include <cuda_bf16.h>
#include <math.h>
#include <cstdint>

#define BB 512
#define CC 12
#define WW 4
#define FF 512
#define NN 2048      // B*W
#define G3 1536      // 3*F
#define MROWS 24576  // C*N rows

// ---------------- scratch (device globals; no allocation allowed) ----------
__device__ float g_xW [MROWS * G3];    // [C][N][3F] input gate preacts
__device__ float g_hgp[3 * NN * G3];   // split-K partials for recurrent GEMM
__device__ float g_hs [CC * NN * FF];  // [C][N][F]  h after each step
__device__ float g_y1 [BB * CC * FF];
__device__ float g_y2 [BB * CC];
__device__ float g_am [CC * CC];
__device__ float g_cheb[4 * CC * CC];
__device__ float g_h1 [MROWS * FF];    // [C][N][F]
__device__ float g_h2 [MROWS * FF];
__device__ float g_supp[MROWS * FF];
__device__ float g_pool[BB * CC * FF]; // [B, C*F]
__device__ float g_fcpart[8 * 512 * 512];
__device__ float g_z1 [BB * 512];
__device__ float g_z2 [BB * 512];
// bf16 hi/lo planes for tensor-core GEMMs
__device__ __nv_bfloat16 g_axh [MROWS * FF], g_axl [MROWS * FF];   // gathered x
__device__ __nv_bfloat16 g_hbh [CC * NN * FF], g_hbl [CC * NN * FF]; // GRU h
__device__ __nv_bfloat16 g_h1bh[MROWS * FF], g_h1bl[MROWS * FF];   // GCN h1
__device__ __nv_bfloat16 g_wihh[G3 * FF], g_wihl[G3 * FF];
__device__ __nv_bfloat16 g_whhh[G3 * FF], g_whhl[G3 * FF];
__device__ __nv_bfloat16 g_g0h [FF * FF], g_g0l [FF * FF];         // gcnw0^T [N,K]
__device__ __nv_bfloat16 g_g1h [FF * FF], g_g1l [FF * FF];         // gcnw1^T [N,K]

__device__ __forceinline__ void mma16816(float* d, const uint32_t* a, const uint32_t* b) {
    asm volatile(
        "mma.sync.aligned.m16n8k16.row.col.f32.bf16.bf16.f32 "
        "{%0,%1,%2,%3}, {%4,%5,%6,%7}, {%8,%9}, {%0,%1,%2,%3};\n"
        : "+f"(d[0]), "+f"(d[1]), "+f"(d[2]), "+f"(d[3])
        : "r"(a[0]), "r"(a[1]), "r"(a[2]), "r"(a[3]), "r"(b[0]), "r"(b[1]));
}
__device__ __forceinline__ void ldm_x4(uint32_t* r, uint32_t addr) {
    asm volatile("ldmatrix.sync.aligned.m8n8.x4.shared.b16 {%0,%1,%2,%3}, [%4];"
        : "=r"(r[0]), "=r"(r[1]), "=r"(r[2]), "=r"(r[3]) : "r"(addr));
}
__device__ __forceinline__ void split_bf(float v, __nv_bfloat16& h, __nv_bfloat16& l) {
    h = __float2bfloat16(v);
    l = __float2bfloat16(v - __bfloat162float(h));
}

// ================= HMMA bf16 hi/lo split GEMM (fused 3-combo) ===============
// D[M,N] fp32 = (Ah+Al)*(Bh+Bl)^T - Al*Bl^T  (lo*lo dropped)
// 3-stage single-barrier cp.async pipeline; dense 64B rows with chunk-XOR
// swizzle: off(r, k) = r*64 + (((k>>3) ^ (r&3))<<4) + (k&7)*2  — conflict-free.
// kSplit>1: grid.z splits the K chunk range (uneven allowed); partial z -> C + z*M*N.
#define MATB 8192                    // bytes per matrix tile (128 rows x 64B)
#define STAGE4 (4 * MATB)            // Ah|Al|Bh|Bl  = 32768 bytes
#define GEMM_SMEM (3 * STAGE4)       // 98304 bytes (3 stages)

__global__ void __launch_bounds__(256, 2)
gemmMMA(const __nv_bfloat16* __restrict__ Ah, const __nv_bfloat16* __restrict__ Al,
        const __nv_bfloat16* __restrict__ Bh, const __nv_bfloat16* __restrict__ Bl,
        const float* __restrict__ bias, float* __restrict__ C, int M, int N, int K,
        int kSplit)
{
    extern __shared__ __align__(16) char dyn[];
    const uint32_t Su32 = (uint32_t)__cvta_generic_to_shared(dyn);

    const int tid = threadIdx.x, wid = tid >> 5, lane = tid & 31;
    const int wm = wid & 3, wn = wid >> 2;
    const int bm = blockIdx.y * 128, bn = blockIdx.x * 128;
    const int r = lane >> 2, cq = lane & 3;

    const __nv_bfloat16* mat[4] = {
        Ah + (size_t)bm * K, Al + (size_t)bm * K,
        Bh + (size_t)bn * K, Bl + (size_t)bn * K };
    const int KCH = K >> 5;
    const int cps = KCH / kSplit, rem = KCH % kSplit;
    const int z = blockIdx.z;
    const int c0 = z * cps + (z < rem ? z : rem);
    const int c1 = c0 + cps + (z < rem ? 1 : 0);
    C += (size_t)z * M * N;

    float acc[2][8][4];
    #pragma unroll
    for (int mi = 0; mi < 2; mi++)
        #pragma unroll
        for (int ni = 0; ni < 8; ni++)
            #pragma unroll
            for (int q = 0; q < 4; q++) acc[mi][ni][q] = 0.f;

    // prefetch: thread -> (row = tid>>2 [0..63] + i*64, chunk = tid&3)
    const int prow = tid >> 2, pch = tid & 3;
    auto prefetch = [&](int c) {
        const int k0 = c << 5;
        const uint32_t st = (uint32_t)((c % 3) * STAGE4);
        #pragma unroll
        for (int m = 0; m < 4; m++) {
            #pragma unroll
            for (int i = 0; i < 2; i++) {
                const int row = prow + i * 64;
                const uint32_t dst = Su32 + st + (uint32_t)m * MATB +
                                     (uint32_t)row * 64 +
                                     ((uint32_t)(pch ^ (row & 3)) << 4);
                const __nv_bfloat16* src = mat[m] + (size_t)row * K + k0 + pch * 8;
                asm volatile("cp.async.cg.shared.global [%0], [%1], 16;"
                             :: "r"(dst), "l"(src) : "memory");
            }
        }
        asm volatile("cp.async.commit_group;" ::: "memory");
    };

    // per-lane ldmatrix address pieces
    const int a_row = lane & 15;            // row within 16-row block
    const int a_sel = lane >> 4;            // 16B chunk select (0/1)
    const int b_row = ((lane >> 4) << 3) + (lane & 7);
    const int b_sel = (lane >> 3) & 1;
    const int lxor = lane & 3;              // (row & 3) for both A and B phases

    prefetch(c0);
    if (c0 + 1 < c1) prefetch(c0 + 1);
    for (int c = c0; c < c1; c++) {
        if (c + 1 < c1) asm volatile("cp.async.wait_group 1;" ::: "memory");
        else            asm volatile("cp.async.wait_group 0;" ::: "memory");
        __syncthreads();                     // publishes chunk c; retires c-1 readers
        if (c + 2 < c1) prefetch(c + 2);

        const uint32_t S = Su32 + (uint32_t)((c % 3) * STAGE4);
        const uint32_t SAh = S, SAl = S + MATB, SBh = S + 2 * MATB, SBl = S + 3 * MATB;
        #pragma unroll
        for (int ks = 0; ks < 2; ks++) {
            const uint32_t axor = (uint32_t)((ks * 2 + a_sel) ^ lxor) << 4;
            const uint32_t bxor = (uint32_t)((ks * 2 + b_sel) ^ lxor) << 4;
            uint32_t ah[2][4], al[2][4], bf[8][2];
            #pragma unroll
            for (int mi = 0; mi < 2; mi++) {
                const uint32_t ra = (uint32_t)(wm * 32 + mi * 16 + a_row) * 64 + axor;
                ldm_x4(ah[mi], SAh + ra);
            }
            #pragma unroll
            for (int nj = 0; nj < 4; nj++) {
                const uint32_t rb = (uint32_t)(wn * 64 + nj * 16 + b_row) * 64 + bxor;
                uint32_t q[4];
                ldm_x4(q, SBh + rb);
                bf[2 * nj][0] = q[0]; bf[2 * nj][1] = q[1];
                bf[2 * nj + 1][0] = q[2]; bf[2 * nj + 1][1] = q[3];
            }
            #pragma unroll
            for (int mi = 0; mi < 2; mi++)
                #pragma unroll
                for (int ni = 0; ni < 8; ni++)
                    mma16816(acc[mi][ni], ah[mi], bf[ni]);
            #pragma unroll
            for (int mi = 0; mi < 2; mi++) {
                const uint32_t ra = (uint32_t)(wm * 32 + mi * 16 + a_row) * 64 + axor;
                ldm_x4(al[mi], SAl + ra);
            }
            #pragma unroll
            for (int mi = 0; mi < 2; mi++)
                #pragma unroll
                for (int ni = 0; ni < 8; ni++)
                    mma16816(acc[mi][ni], al[mi], bf[ni]);
            #pragma unroll
            for (int nj = 0; nj < 4; nj++) {
                const uint32_t rb = (uint32_t)(wn * 64 + nj * 16 + b_row) * 64 + bxor;
                uint32_t q[4];
                ldm_x4(q, SBl + rb);
                bf[2 * nj][0] = q[0]; bf[2 * nj][1] = q[1];
                bf[2 * nj + 1][0] = q[2]; bf[2 * nj + 1][1] = q[3];
            }
            #pragma unroll
            for (int mi = 0; mi < 2; mi++)
                #pragma unroll
                for (int ni = 0; ni < 8; ni++)
                    mma16816(acc[mi][ni], ah[mi], bf[ni]);
        }
    }

    #pragma unroll
    for (int mi = 0; mi < 2; mi++) {
        const int row0 = bm + wm * 32 + mi * 16 + r;
        #pragma unroll
        for (int ni = 0; ni < 8; ni++) {
            const int col = bn + wn * 64 + ni * 8 + cq * 2;
            float b0 = 0.f, b1 = 0.f;
            if (bias) { b0 = bias[col]; b1 = bias[col + 1]; }
            float2 v0 = make_float2(acc[mi][ni][0] + b0, acc[mi][ni][1] + b1);
            float2 v1 = make_float2(acc[mi][ni][2] + b0, acc[mi][ni][3] + b1);
            *(float2*)&C[(size_t)row0 * N + col] = v0;
            *(float2*)&C[(size_t)(row0 + 8) * N + col] = v1;
        }
    }
}

// ================= fp32 128x128 GEMM (head only) ============================
template<bool TRANSB, int AMAP, int EPI>
__global__ void __launch_bounds__(256, 2)
gemm128(const float* __restrict__ A, const float* __restrict__ B,
        const float* __restrict__ bias, float* __restrict__ C,
        int M, int N, int K, int kChunk)
{
    __shared__ float As[16][132];
    __shared__ float Bs[16][132];
    const int tid = threadIdx.x;
    const int tx = tid & 15, ty = tid >> 4;
    const int bm = blockIdx.y * 128, bn = blockIdx.x * 128;
    int ks = 0, ke = K;
    if (kChunk > 0) {
        ks = blockIdx.z * kChunk; ke = ks + kChunk;
        C += (size_t)blockIdx.z * M * N;
    }
    const int lr = tid >> 2;
    const int lc = (tid & 3) * 4;
    const int bR = tid >> 5;
    const int bC = (tid & 31) * 4;
    size_t aRow0 = (size_t)(bm + lr), aRow1 = (size_t)(bm + lr + 64);

    float4 pa0, pa1, pb0, pb1;
    auto loadg = [&](int k0) {
        pa0 = *(const float4*)&A[aRow0 * K + k0 + lc];
        pa1 = *(const float4*)&A[aRow1 * K + k0 + lc];
        if (TRANSB) {
            pb0 = *(const float4*)&B[(size_t)(bn + lr) * K + k0 + lc];
            pb1 = *(const float4*)&B[(size_t)(bn + lr + 64) * K + k0 + lc];
        } else {
            pb0 = *(const float4*)&B[(size_t)(k0 + bR) * N + bn + bC];
            pb1 = *(const float4*)&B[(size_t)(k0 + bR + 8) * N + bn + bC];
        }
    };
    unsigned long long acc[8][4];
    #pragma unroll
    for (int i = 0; i < 8; i++)
        #pragma unroll
        for (int j = 0; j < 4; j++) acc[i][j] = 0ULL;
    loadg(ks);
    for (int k0 = ks; k0 < ke; k0 += 16) {
        As[lc + 0][lr] = pa0.x; As[lc + 1][lr] = pa0.y;
        As[lc + 2][lr] = pa0.z; As[lc + 3][lr] = pa0.w;
        As[lc + 0][lr + 64] = pa1.x; As[lc + 1][lr + 64] = pa1.y;
        As[lc + 2][lr + 64] = pa1.z; As[lc + 3][lr + 64] = pa1.w;
        if (TRANSB) {
            Bs[lc + 0][lr] = pb0.x; Bs[lc + 1][lr] = pb0.y;
            Bs[lc + 2][lr] = pb0.z; Bs[lc + 3][lr] = pb0.w;
            Bs[lc + 0][lr + 64] = pb1.x; Bs[lc + 1][lr + 64] = pb1.y;
            Bs[lc + 2][lr + 64] = pb1.z; Bs[lc + 3][lr + 64] = pb1.w;
        } else {
            *(float4*)&Bs[bR][bC]     = pb0;
            *(float4*)&Bs[bR + 8][bC] = pb1;
        }
        __syncthreads();
        if (k0 + 16 < ke) loadg(k0 + 16);
        #pragma unroll
        for (int k = 0; k < 16; k++) {
            float4 a0 = *(const float4*)&As[k][ty * 4];
            float4 a1 = *(const float4*)&As[k][64 + ty * 4];
            ulonglong2 b0 = *(const ulonglong2*)&Bs[k][tx * 4];
            ulonglong2 b1 = *(const ulonglong2*)&Bs[k][64 + tx * 4];
            float ar[8] = {a0.x, a0.y, a0.z, a0.w, a1.x, a1.y, a1.z, a1.w};
            unsigned long long bp[4] = {b0.x, b0.y, b1.x, b1.y};
            #pragma unroll
            for (int i = 0; i < 8; i++) {
                unsigned long long ad;
                asm("mov.b64 %0, {%1, %1};" : "=l"(ad) : "f"(ar[i]));
                #pragma unroll
                for (int j = 0; j < 4; j++)
                    asm("fma.rn.f32x2 %0, %1, %2, %0;"
                        : "+l"(acc[i][j]) : "l"(ad), "l"(bp[j]));
            }
        }
        __syncthreads();
    }
    #pragma unroll
    for (int i = 0; i < 8; i++) {
        int gm = bm + ((i < 4) ? (ty * 4 + i) : (60 + ty * 4 + i));
        float v[8];
        #pragma unroll
        for (int j = 0; j < 4; j++)
            asm("mov.b64 {%0, %1}, %2;"
                : "=f"(v[2 * j]), "=f"(v[2 * j + 1]) : "l"(acc[i][j]));
        #pragma unroll
        for (int h = 0; h < 2; h++) {
            int gn = bn + (h ? 64 + tx * 4 : tx * 4);
            float t0 = v[h * 4], t1 = v[h * 4 + 1], t2 = v[h * 4 + 2], t3 = v[h * 4 + 3];
            if (EPI >= 1) {
                t0 += bias[gn + 0]; t1 += bias[gn + 1];
                t2 += bias[gn + 2]; t3 += bias[gn + 3];
            }
            float4 o; o.x = t0; o.y = t1; o.z = t2; o.w = t3;
            *(float4*)&C[(size_t)gm * N + gn] = o;
        }
    }
}

// ================= conversions =============================================
__global__ void k_cvt(const float* __restrict__ src, __nv_bfloat16* __restrict__ hi,
                      __nv_bfloat16* __restrict__ lo, int n) {
    int i = blockIdx.x * blockDim.x + threadIdx.x;
    if (i >= n) return;
    split_bf(src[i], hi[i], lo[i]);
}

// gcn weight [K,N] -> planes [N,K]
__global__ void k_cvtT(const float* __restrict__ W, __nv_bfloat16* __restrict__ hi,
                       __nv_bfloat16* __restrict__ lo) {
    int i = blockIdx.x * blockDim.x + threadIdx.x;
    if (i >= FF * FF) return;
    int n = i >> 9, k = i & 511;
    split_bf(W[k * FF + n], hi[i], lo[i]);
}

// gather x -> A planes [C][N][F]
__global__ void k_cvt_x(const float* __restrict__ x) {
    int idx = blockIdx.x * blockDim.x + threadIdx.x;
    if (idx >= MROWS * FF) return;
    int f = idx & 511;
    int r = idx >> 9;
    int t = r / NN, n = r - t * NN;
    int b = n >> 2, w = n & 3;
    float v = x[(((size_t)b * CC + t) * WW + w) * FF + f];
    split_bf(v, g_axh[idx], g_axl[idx]);
}

// ================= GRU gates (vectorized float4) ============================
__device__ __forceinline__ void gate_store4(size_t o, const float* h) {
    *(float4*)&g_hs[o] = make_float4(h[0], h[1], h[2], h[3]);
    __align__(8) __nv_bfloat16 hh[4], hl[4];
    #pragma unroll
    for (int i = 0; i < 4; i++) split_bf(h[i], hh[i], hl[i]);
    *(uint2*)&g_hbh[o] = *(uint2*)hh;
    *(uint2*)&g_hbl[o] = *(uint2*)hl;
}

__global__ void k_gru_gate0(const float* __restrict__ bhh) {
    int idx = blockIdx.x * blockDim.x + threadIdx.x;
    if (idx >= NN * FF / 4) return;
    int n = idx >> 7, f = (idx & 127) * 4;
    const float* xw = g_xW + (size_t)n * G3;
    float4 xr = *(const float4*)&xw[f];
    float4 xz = *(const float4*)&xw[512 + f];
    float4 xn = *(const float4*)&xw[1024 + f];
    float4 br = *(const float4*)&bhh[f];
    float4 bz = *(const float4*)&bhh[512 + f];
    float4 bn = *(const float4*)&bhh[1024 + f];
    float h[4];
    #pragma unroll
    for (int i = 0; i < 4; i++) {
        float xri = ((const float*)&xr)[i] + ((const float*)&br)[i];
        float xzi = ((const float*)&xz)[i] + ((const float*)&bz)[i];
        float xni = ((const float*)&xn)[i];
        float bni = ((const float*)&bn)[i];
        float r = 1.f / (1.f + expf(-xri));
        float z = 1.f / (1.f + expf(-xzi));
        float nv = tanhf(xni + r * bni);
        h[i] = (1.f - z) * nv;
    }
    gate_store4((size_t)n * FF + f, h);
}

// t>0: sums the three split-K partials of h_prev @ whh^T, adds bhh, gate math.
__global__ void k_gru_gate(int t, const float* __restrict__ bhh) {
    int idx = blockIdx.x * blockDim.x + threadIdx.x;
    if (idx >= NN * FF / 4) return;
    int n = idx >> 7, f = (idx & 127) * 4;
    const size_t base = (size_t)n * G3;
    const float* p0 = g_hgp + base;
    const float* p1 = g_hgp + (size_t)NN * G3 + base;
    const float* p2 = g_hgp + (size_t)2 * NN * G3 + base;
    float hr[4], hz[4], hn[4];
    #pragma unroll
    for (int g = 0; g < 3; g++) {
        float* dst = (g == 0) ? hr : (g == 1) ? hz : hn;
        const int off = g * 512 + f;
        float4 a = *(const float4*)&p0[off];
        float4 b = *(const float4*)&p1[off];
        float4 c = *(const float4*)&p2[off];
        float4 d = *(const float4*)&bhh[off];
        dst[0] = a.x + b.x + c.x + d.x;
        dst[1] = a.y + b.y + c.y + d.y;
        dst[2] = a.z + b.z + c.z + d.z;
        dst[3] = a.w + b.w + c.w + d.w;
    }
    const float* xw = g_xW + ((size_t)t * NN + n) * G3;
    float4 xr = *(const float4*)&xw[f];
    float4 xz = *(const float4*)&xw[512 + f];
    float4 xn = *(const float4*)&xw[1024 + f];
    float4 hp = *(const float4*)&g_hs[((size_t)(t - 1) * NN + n) * FF + f];
    float h[4];
    #pragma unroll
    for (int i = 0; i < 4; i++) {
        float r = 1.f / (1.f + expf(-(((const float*)&xr)[i] + hr[i])));
        float z = 1.f / (1.f + expf(-(((const float*)&xz)[i] + hz[i])));
        float nv = tanhf(((const float*)&xn)[i] + r * hn[i]);
        h[i] = (1.f - z) * nv + z * ((const float*)&hp)[i];
    }
    gate_store4(((size_t)t * NN + n) * FF + f, h);
}

// ================= graph learning ==========================================
__global__ void k_y1(const float* __restrict__ w, const float* __restrict__ b0) {
    int idx = blockIdx.x * blockDim.x + threadIdx.x;
    if (idx >= BB * CC * FF) return;
    int f = idx & 511;
    int r = idx >> 9;
    int c = r % 12, b = r / 12;
    float s = b0[0];
    #pragma unroll
    for (int wi = 0; wi < 4; wi++)
        s += g_hs[((size_t)c * NN + (b * 4 + wi)) * FF + f] * w[wi];
    g_y1[idx] = fmaxf(s, 0.f);
}

__global__ void k_y2(const float* __restrict__ w, const float* __restrict__ b1) {
    int r = blockIdx.x;
    float s = 0.f;
    for (int f = threadIdx.x; f < 512; f += 128)
        s += g_y1[(size_t)r * 512 + f] * w[f];
    __shared__ float red[4];
    for (int o = 16; o; o >>= 1) s += __shfl_down_sync(0xffffffffu, s, o);
    if ((threadIdx.x & 31) == 0) red[threadIdx.x >> 5] = s;
    __syncthreads();
    if (threadIdx.x == 0)
        g_y2[r] = fmaxf(red[0] + red[1] + red[2] + red[3] + b1[0], 0.f);
}

__global__ void k_y3mean(const float* __restrict__ w2, const float* __restrict__ b2) {
    int k = blockIdx.x;
    float wl[12];
    #pragma unroll
    for (int c = 0; c < 12; c++) wl[c] = w2[k * 12 + c];
    float bk = b2[k];
    float s = 0.f;
    for (int b = threadIdx.x; b < 512; b += 256) {
        float v = bk;
        #pragma unroll
        for (int c = 0; c < 12; c++) v += g_y2[b * 12 + c] * wl[c];
        s += fmaxf(v, 0.f);
    }
    __shared__ float red[8];
    for (int o = 16; o; o >>= 1) s += __shfl_down_sync(0xffffffffu, s, o);
    if ((threadIdx.x & 31) == 0) red[threadIdx.x >> 5] = s;
    __syncthreads();
    if (threadIdx.x == 0) {
        float t = 0.f;
        #pragma unroll
        for (int i = 0; i < 8; i++) t += red[i];
        g_am[k] = t * (1.f / 512.f);
    }
}

__global__ void k_cheb() {
    __shared__ float adj[144], lap[144], L2s[144], deg[12], dh[12];
    int t = threadIdx.x;
    if (t < 144) adj[t] = fmaxf(g_am[t], 0.f);
    __syncthreads();
    if (t < 12) {
        float s = 0.f;
        #pragma unroll
        for (int j = 0; j < 12; j++) s += adj[t * 12 + j];
        deg[t] = s;
        dh[t] = 1.f / (sqrtf(s) + 1e-7f);
    }
    __syncthreads();
    if (t < 144) {
        int i = t / 12, j = t % 12;
        float as = 0.5f * (adj[i * 12 + j] + adj[j * 12 + i]);
        lap[t] = dh[i] * (((i == j) ? deg[i] : 0.f) - as) * dh[j];
    }
    __syncthreads();
    if (t < 144) {
        int i = t / 12, j = t % 12;
        float s = 0.f;
        #pragma unroll
        for (int k = 0; k < 12; k++) s += lap[i * 12 + k] * lap[k * 12 + j];
        L2s[t] = 2.f * s;
    }
    __syncthreads();
    if (t < 144) {
        int i = t / 12, j = t % 12;
        float s = 0.f;
        #pragma unroll
        for (int k = 0; k < 12; k++) s += lap[i * 12 + k] * L2s[k * 12 + j];
        g_cheb[t]       = 0.f;
        g_cheb[144 + t] = lap[t];
        g_cheb[288 + t] = L2s[t];
        g_cheb[432 + t] = 2.f * s - lap[t];
    }
}

// ============ GCN: cheb mix + bias + relu + residual ([C][N][F]) ============
__global__ void k_gcnpost(const float* __restrict__ Hres, const float* __restrict__ gcnb,
                          float* __restrict__ Hout,
                          __nv_bfloat16* __restrict__ Ohi, __nv_bfloat16* __restrict__ Olo) {
    int blk = blockIdx.x;
    int n = blk >> 2;
    int chunk = blk & 3;
    int w = n & 3;
    int f = chunk * 128 + threadIdx.x;
    __shared__ float s[12][129];
    __shared__ float ch[144];
    for (int i = threadIdx.x; i < 144; i += 128) ch[i] = g_cheb[w * 144 + i];
    #pragma unroll
    for (int j = 0; j < 12; j++)
        s[j][threadIdx.x] = g_supp[((size_t)j * NN + n) * 512 + f];
    __syncthreads();
    float bias = gcnb[f];
    #pragma unroll
    for (int i = 0; i < 12; i++) {
        float acc = bias;
        #pragma unroll
        for (int j = 0; j < 12; j++)
            acc = fmaf(ch[i * 12 + j], s[j][threadIdx.x], acc);
        size_t o = ((size_t)i * NN + n) * 512 + f;
        float hv = fmaxf(acc, 0.f) + Hres[o];
        Hout[o] = hv;
        if (Ohi) split_bf(hv, Ohi[o], Olo[o]);
    }
}

// ================= pool over W + flatten ====================================
__global__ void k_pool() {
    int idx = blockIdx.x * blockDim.x + threadIdx.x;
    if (idx >= BB * CC * FF) return;
    int f = idx & 511;
    int r = idx >> 9;
    int c = r % 12, b = r / 12;
    float s = 0.f;
    #pragma unroll
    for (int w = 0; w < 4; w++) {
        size_t o = ((size_t)c * NN + (b * 4 + w)) * 512 + f;
        s += g_hs[o] + g_h2[o];
    }
    g_pool[idx] = s;
}

// ================= split-K reduce + leaky + BN ==============================
__global__ void k_fcreduce(int S, const float* __restrict__ bias,
                           const float* __restrict__ bng, const float* __restrict__ bnb,
                           const float* __restrict__ bnm, const float* __restrict__ bnv,
                           float* __restrict__ out) {
    int idx = blockIdx.x * blockDim.x + threadIdx.x;
    if (idx >= 512 * 512) return;
    float s = 0.f;
    for (int p = 0; p < S; p++) s += g_fcpart[(size_t)p * 512 * 512 + idx];
    int c = idx & 511;
    s += bias[c];
    s = s > 0.f ? s : 0.01f * s;
    s = (s - bnm[c]) * rsqrtf(bnv[c] + 1e-5f) * bng[c] + bnb[c];
    out[idx] = s;
}

// ================= fc3 (N=4) ================================================
__global__ void k_fc3(const float* __restrict__ w, const float* __restrict__ b,
                      float* __restrict__ out) {
    int bb = blockIdx.x;
    float s0 = 0.f, s1 = 0.f, s2 = 0.f, s3 = 0.f;
    for (int j = threadIdx.x; j < 512; j += 128) {
        float v = g_z2[bb * 512 + j];
        const float* wr = w + j * 4;
        s0 += v * wr[0]; s1 += v * wr[1]; s2 += v * wr[2]; s3 += v * wr[3];
    }
    __shared__ float red[4][4];
    for (int o = 16; o; o >>= 1) {
        s0 += __shfl_down_sync(0xffffffffu, s0, o);
        s1 += __shfl_down_sync(0xffffffffu, s1, o);
        s2 += __shfl_down_sync(0xffffffffu, s2, o);
        s3 += __shfl_down_sync(0xffffffffu, s3, o);
    }
    int wid = threadIdx.x >> 5;
    if ((threadIdx.x & 31) == 0) {
        red[wid][0] = s0; red[wid][1] = s1; red[wid][2] = s2; red[wid][3] = s3;
    }
    __syncthreads();
    if (threadIdx.x < 4) {
        float t = red[0][threadIdx.x] + red[1][threadIdx.x] +
                  red[2][threadIdx.x] + red[3][threadIdx.x];
        out[bb * 4 + threadIdx.x] = t + b[threadIdx.x];
    }
}

// ================= launch ===================================================
extern "C" void kernel_launch(void* const* d_in, const int* in_sizes, int n_in,
                              void* d_out, int out_size) {
    const float* x    = (const float*)d_in[0];
    const float* wih  = (const float*)d_in[1];
    const float* whh  = (const float*)d_in[2];
    const float* bih  = (const float*)d_in[3];
    const float* bhh  = (const float*)d_in[4];
    const float* c0w  = (const float*)d_in[5];
    const float* c0b  = (const float*)d_in[6];
    const float* c1w  = (const float*)d_in[7];
    const float* c1b  = (const float*)d_in[8];
    const float* c2w  = (const float*)d_in[9];
    const float* c2b  = (const float*)d_in[10];
    const float* gcnw = (const float*)d_in[11];
    const float* gcnb = (const float*)d_in[12];
    const float* fc1w = (const float*)d_in[13];
    const float* fc1b = (const float*)d_in[14];
    const float* bn1g = (const float*)d_in[15];
    const float* bn1b = (const float*)d_in[16];
    const float* bn1m = (const float*)d_in[17];
    const float* bn1v = (const float*)d_in[18];
    const float* fc2w = (const float*)d_in[19];
    const float* fc2b = (const float*)d_in[20];
    const float* bn2g = (const float*)d_in[21];
    const float* bn2b = (const float*)d_in[22];
    const float* bn2m = (const float*)d_in[23];
    const float* bn2v = (const float*)d_in[24];
    const float* fc3w = (const float*)d_in[25];
    const float* fc3b = (const float*)d_in[26];
    float* out = (float*)d_out;

    cudaFuncSetAttribute(gemmMMA, cudaFuncAttributeMaxDynamicSharedMemorySize, GEMM_SMEM);

    float *p_xW, *p_hgp, *p_hs, *p_h1, *p_h2, *p_supp, *p_pool, *p_part, *p_z1, *p_z2;
    cudaGetSymbolAddress((void**)&p_xW,  g_xW);
    cudaGetSymbolAddress((void**)&p_hgp, g_hgp);
    cudaGetSymbolAddress((void**)&p_hs,  g_hs);
    cudaGetSymbolAddress((void**)&p_h1,  g_h1);
    cudaGetSymbolAddress((void**)&p_h2,  g_h2);
    cudaGetSymbolAddress((void**)&p_supp, g_supp);
    cudaGetSymbolAddress((void**)&p_pool, g_pool);
    cudaGetSymbolAddress((void**)&p_part, g_fcpart);
    cudaGetSymbolAddress((void**)&p_z1,  g_z1);
    cudaGetSymbolAddress((void**)&p_z2,  g_z2);
    __nv_bfloat16 *p_axh, *p_axl, *p_hbh, *p_hbl, *p_h1bh, *p_h1bl;
    __nv_bfloat16 *p_wihh, *p_wihl, *p_whhh, *p_whhl, *p_g0h, *p_g0l, *p_g1h, *p_g1l;
    cudaGetSymbolAddress((void**)&p_axh,  g_axh);
    cudaGetSymbolAddress((void**)&p_axl,  g_axl);
    cudaGetSymbolAddress((void**)&p_hbh,  g_hbh);
    cudaGetSymbolAddress((void**)&p_hbl,  g_hbl);
    cudaGetSymbolAddress((void**)&p_h1bh, g_h1bh);
    cudaGetSymbolAddress((void**)&p_h1bl, g_h1bl);
    cudaGetSymbolAddress((void**)&p_wihh, g_wihh);
    cudaGetSymbolAddress((void**)&p_wihl, g_wihl);
    cudaGetSymbolAddress((void**)&p_whhh, g_whhh);
    cudaGetSymbolAddress((void**)&p_whhl, g_whhl);
    cudaGetSymbolAddress((void**)&p_g0h,  g_g0h);
    cudaGetSymbolAddress((void**)&p_g0l,  g_g0l);
    cudaGetSymbolAddress((void**)&p_g1h,  g_g1h);
    cudaGetSymbolAddress((void**)&p_g1l,  g_g1l);

    // 0) input-side conversions
    k_cvt_x<<<(MROWS * FF + 255) / 256, 256>>>(x);
    k_cvt<<<(G3 * FF + 255) / 256, 256>>>(wih, p_wihh, p_wihl, G3 * FF);
    k_cvt<<<(G3 * FF + 255) / 256, 256>>>(whh, p_whhh, p_whhl, G3 * FF);

    // 1) input-gate preacts: [24576,1536] = x * wih^T + bih  (HMMA)
    gemmMMA<<<dim3(G3 / 128, MROWS / 128), 256, GEMM_SMEM>>>(
        p_axh, p_axl, p_wihh, p_wihl, bih, p_xW, MROWS, G3, FF, 1);

    // 2) 12 recurrent steps: split-K=3 GEMM (576 blocks)
    k_gru_gate0<<<(NN * FF / 4 + 255) / 256, 256>>>(bhh);
    for (int t = 1; t < CC; t++) {
        gemmMMA<<<dim3(G3 / 128, NN / 128, 3), 256, GEMM_SMEM>>>(
            p_hbh + (size_t)(t - 1) * NN * FF, p_hbl + (size_t)(t - 1) * NN * FF,
            p_whhh, p_whhl, nullptr, p_hgp, NN, G3, FF, 3);
        k_gru_gate<<<(NN * FF / 4 + 255) / 256, 256>>>(t, bhh);
    }

    // 3) graph learning -> chebyshev basis (+ GCN weight conversion)
    k_y1<<<(BB * CC * FF + 255) / 256, 256>>>(c0w, c0b);
    k_y2<<<BB * CC, 128>>>(c1w, c1b);
    k_y3mean<<<CC * CC, 256>>>(c2w, c2b);
    k_cheb<<<1, 160>>>();
    k_cvtT<<<(FF * FF + 255) / 256, 256>>>(gcnw, p_g0h, p_g0l);
    k_cvtT<<<(FF * FF + 255) / 256, 256>>>(gcnw + FF * FF, p_g1h, p_g1l);

    // 4) GCN layer 0
    gemmMMA<<<dim3(FF / 128, MROWS / 128), 256, GEMM_SMEM>>>(
        p_hbh, p_hbl, p_g0h, p_g0l, nullptr, p_supp, MROWS, FF, FF, 1);
    k_gcnpost<<<NN * 4, 128>>>(p_hs, gcnb, p_h1, p_h1bh, p_h1bl);

    // 5) GCN layer 1
    gemmMMA<<<dim3(FF / 128, MROWS / 128), 256, GEMM_SMEM>>>(
        p_h1bh, p_h1bl, p_g1h, p_g1l, nullptr, p_supp, MROWS, FF, FF, 1);
    k_gcnpost<<<NN * 4, 128>>>(p_h1, gcnb + FF, p_h2, nullptr, nullptr);

    // 6) pool over W -> [B, C*F]
    k_pool<<<(BB * CC * FF + 255) / 256, 256>>>();

    // 7) classifier head (fp32 split-K)
    gemm128<false, 0, 0><<<dim3(4, 4, 8), 256>>>(
        p_pool, fc1w, nullptr, p_part, BB, 512, CC * FF, 768);
    k_fcreduce<<<1024, 256>>>(8, fc1b, bn1g, bn1b, bn1m, bn1v, p_z1);
    gemm128<false, 0, 0><<<dim3(4, 4, 4), 256>>>(
        p_z1, fc2w, nullptr, p_part, BB, 512, 512, 128);
    k_fcreduce<<<1024, 256>>>(4, fc2b, bn2g, bn2b, bn2m, bn2v, p_z2);
    k_fc3<<<BB, 128>>>(fc3w, fc3b, out);
}